// round 5
// baseline (speedup 1.0000x reference)
#include <cuda_runtime.h>

#define NN 50000
#define CC 8
#define DD 64
#define EE 100000
#define PITCH 68      // padded row for 64-wide matrices
#define QPITCH 196    // padded row for qkv (192 cols)

// k-dim permutation: storage position p in each 8-block holds column inv(p),
// inv(p) = (p>>1) + (p&1)*4 ; pos(c) = ((c&3)<<1) | ((c>>2)&1)
// => fragment pairs (k, k+4) are adjacent -> float2 loads.

// -------- scratch (device globals: allocation-free) --------
__device__ float g_hA[(size_t)NN * 512];
__device__ float g_hB[(size_t)NN * 512];
__device__ float g_inv[NN];
__device__ int   g_any;

// ---------------- setup kernels ----------------

__global__ void setup0_kernel() {
    size_t i = (size_t)blockIdx.x * blockDim.x + threadIdx.x;
    if (i == 0) g_any = 0;
    if (i < NN) g_inv[i] = 0.f;
    if (i < (size_t)NN * 128) ((float4*)g_hB)[i] = make_float4(0.f, 0.f, 0.f, 0.f);
}

__global__ void detect_kernel(const int* __restrict__ ei) {
    int i = blockIdx.x * blockDim.x + threadIdx.x;
    int v = 0;
    for (int k = i; k < EE; k += gridDim.x * blockDim.x) v |= ei[2 * k + 1];
    if (v) atomicOr(&g_any, 1);
}

__global__ void embed_kernel(const float* __restrict__ x,
                             const float* __restrict__ nw,
                             const float* __restrict__ nb) {
    int i = blockIdx.x * blockDim.x + threadIdx.x;
    if (i < NN * 512) {
        int n = i >> 9;
        int r = i & 511;
        g_hA[i] = x[n * 8 + (r >> 6)] * nw[r] + nb[r];
    }
}

__global__ void count_kernel(const int* __restrict__ ei) {
    int e = blockIdx.x * blockDim.x + threadIdx.x;
    if (e < EE) {
        int is64 = (g_any == 0);
        int t = is64 ? ei[2 * (EE + e)] : ei[EE + e];
        atomicAdd(&g_inv[t], 1.0f);
    }
}

__global__ void fin_cnt_kernel() {
    int i = blockIdx.x * blockDim.x + threadIdx.x;
    if (i < NN) g_inv[i] = 1.0f / fmaxf(g_inv[i], 1.0f);
}

__global__ void zeroA_kernel() {
    size_t i = (size_t)blockIdx.x * blockDim.x + threadIdx.x;
    if (i < (size_t)NN * 128) ((float4*)g_hA)[i] = make_float4(0.f, 0.f, 0.f, 0.f);
}

// ---------------- tf32 mma helpers ----------------

__device__ __forceinline__ unsigned f2tf(float x) {
    unsigned r;
    asm("cvt.rna.tf32.f32 %0, %1;" : "=r"(r) : "f"(x));
    return r;
}

__device__ __forceinline__ void mma_tf32(float& c0, float& c1, float& c2, float& c3,
                                         unsigned a0, unsigned a1, unsigned a2, unsigned a3,
                                         unsigned b0, unsigned b1) {
    asm volatile(
        "mma.sync.aligned.m16n8k8.row.col.f32.tf32.tf32.f32 "
        "{%0,%1,%2,%3}, {%4,%5,%6,%7}, {%8,%9}, {%0,%1,%2,%3};\n"
        : "+f"(c0), "+f"(c1), "+f"(c2), "+f"(c3)
        : "r"(a0), "r"(a1), "r"(a2), "r"(a3), "r"(b0), "r"(b1));
}

// permuted A-fragment load: pairs (k, k+4) adjacent -> float2
__device__ __forceinline__ void load_a(unsigned a[8][4], const float* __restrict__ X,
                                       int xp, int lane) {
    int row = lane >> 2, t2 = (lane & 3) << 1;
    const float* p0 = X + row * xp + t2;
    const float* p1 = X + (row + 8) * xp + t2;
    #pragma unroll
    for (int kb = 0; kb < 8; kb++) {
        float2 u0 = *(const float2*)(p0 + kb * 8);
        float2 u1 = *(const float2*)(p1 + kb * 8);
        a[kb][0] = f2tf(u0.x); a[kb][2] = f2tf(u0.y);
        a[kb][1] = f2tf(u1.x); a[kb][3] = f2tf(u1.y);
    }
}

// EPI: 0 plain, 1 relu, 2 add residual R ; ROWS8: only rows 0..7 stored
// Output/residual buffers are in permuted layout; bias arrays unpermuted.
template<int EPI, bool ROWS8>
__device__ __forceinline__ void gemm_tile(const unsigned a[8][4],
                                          const float* __restrict__ W,
                                          const float* __restrict__ bias,
                                          int jbase,
                                          float* __restrict__ C, int cp,
                                          const float* __restrict__ R, int rp,
                                          int lane) {
    int g = lane >> 2, tg = lane & 3;
    float2 bb = *(const float2*)(bias + jbase + 2 * tg);
    float c0 = bb.x, c1 = bb.y, c2 = bb.x, c3 = bb.y;
    const float* wr = W + (jbase + g) * PITCH;
    #pragma unroll
    for (int kb = 0; kb < 8; kb++) {
        float2 w2 = *(const float2*)(wr + kb * 8 + 2 * tg);
        mma_tf32(c0, c1, c2, c3, a[kb][0], a[kb][1], a[kb][2], a[kb][3],
                 __float_as_uint(w2.x), __float_as_uint(w2.y));
    }
    // store positions: pos(2tg) = ((tg&1)<<2)+(tg>>1), pos(2tg+1) = pos(2tg)+2
    int p0 = jbase + ((tg & 1) << 2) + (tg >> 1);
    int p1 = p0 + 2;
    if (EPI == 2) {
        c0 += R[g * rp + p0];       c1 += R[g * rp + p1];
        c2 += R[(g + 8) * rp + p0]; c3 += R[(g + 8) * rp + p1];
    }
    if (EPI == 1) {
        c0 = fmaxf(c0, 0.f); c1 = fmaxf(c1, 0.f);
        c2 = fmaxf(c2, 0.f); c3 = fmaxf(c3, 0.f);
    }
    C[g * cp + p0] = c0; C[g * cp + p1] = c1;
    if (!ROWS8) { C[(g + 8) * cp + p0] = c2; C[(g + 8) * cp + p1] = c3; }
}

// ---------------- main per-edge transformer kernel ----------------

#define SUBBAR() asm volatile("bar.sync %0, 128;" :: "r"(sub + 1) : "memory")

__global__ void __launch_bounds__(512, 1)
edge_kernel(const int* __restrict__ ei, int dir,
            const float* __restrict__ bpw, const float* __restrict__ bpb,
            const float* __restrict__ ipw, const float* __restrict__ ipb,
            const float* __restrict__ opw, const float* __restrict__ opb,
            const float* __restrict__ ln1g, const float* __restrict__ ln1b,
            const float* __restrict__ ln2g, const float* __restrict__ ln2b,
            const float* __restrict__ w1,  const float* __restrict__ fb1,
            const float* __restrict__ w2,  const float* __restrict__ fb2) {
    extern __shared__ float sm[];
    float* s_ipw = sm;                          // 192*68
    float* s_opw = s_ipw + 192 * PITCH;
    float* s_w1  = s_opw + 64 * PITCH;
    float* s_w2  = s_w1  + 64 * PITCH;
    float* s_bw  = s_w2  + 64 * PITCH;
    float* s_b   = s_bw  + 64 * PITCH;          // 704 floats biases/ln
    float* s_act = s_b + 704;

    const float* hin  = dir ? g_hB : g_hA;
    float*       hout = dir ? g_hA : g_hB;

    const int tid = threadIdx.x;

    // ---- stage weights once: tf32-rounded, k-dim permuted ----
    for (int i = tid; i < 192 * 64; i += 512) {
        int j = i >> 6, k = i & 63;
        int kp = (k & 56) | ((k & 3) << 1) | ((k >> 2) & 1);
        s_ipw[j * PITCH + kp] = __uint_as_float(f2tf(ipw[i]));
    }
    for (int i = tid; i < 64 * 64; i += 512) {
        int j = i >> 6, k = i & 63;
        int kp = (k & 56) | ((k & 3) << 1) | ((k >> 2) & 1);
        int r = j * PITCH + kp;
        s_opw[r] = __uint_as_float(f2tf(opw[i]));
        s_w1[r]  = __uint_as_float(f2tf(w1[i]));
        s_w2[r]  = __uint_as_float(f2tf(w2[i]));
        s_bw[r]  = __uint_as_float(f2tf(bpw[i]));
    }
    for (int i = tid; i < 192; i += 512) s_b[i] = ipb[i];       // unpermuted biases
    if (tid < 64) {
        int kp = (tid & 56) | ((tid & 3) << 1) | ((tid >> 2) & 1);
        s_b[192 + tid] = opb[tid];   // bias: unpermuted
        s_b[256 + tid] = fb1[tid];
        s_b[320 + tid] = fb2[tid];
        s_b[384 + kp]  = ln1g[tid];  // LN1 gamma/beta: permuted (applied in position space)
        s_b[448 + kp]  = ln1b[tid];
        s_b[512 + tid] = ln2g[tid];  // LN2: unpermuted (applied in global-col space)
        s_b[576 + tid] = ln2b[tid];
        s_b[640 + tid] = bpb[tid];   // bias: unpermuted
    }
    __syncthreads();

    const int sub  = tid >> 7;     // 0..3 edge slot
    const int st   = tid & 127;
    const int warp = st >> 5;
    const int lane = st & 31;
    const int g    = lane >> 2, tg = lane & 3;
    float* xs  = s_act + sub * 5888;       // 8*68
    float* xc  = xs + 8 * PITCH;           // 16*68
    float* qv  = xc + 16 * PITCH;          // 16*196 (q 0..63 | k 64..127 | vT 128..191)
    float* ao  = qv + 16 * QPITCH;         // 16*68  (P scratch / attn out / ff hidden)

    const int is64 = (g_any == 0);
    // gather: thread owns permuted positions p0..p0+3 of row r0
    const int r0 = st >> 4;
    const int ppos = (st & 15) << 2;
    const int cgb = (ppos & ~7) + ((ppos >> 2) & 1) * 2;  // global col base (pairs cgb,cgb+1 / cgb+4,cgb+5)
    const int stride4 = gridDim.x * 4;

    // ---- prologue prefetch ----
    bool pv; int ptgt = 0; float pic = 0.f;
    float4 pvi = make_float4(0, 0, 0, 0), pvj = pvi;
    {
        int e = blockIdx.x * 4 + sub;
        pv = e < EE;
        if (pv) {
            int src = is64 ? ei[2 * e]        : ei[e];
            ptgt    = is64 ? ei[2 * (EE + e)] : ei[EE + e];
            pic = g_inv[ptgt];
            const float* bi = hin + (size_t)ptgt * 512 + r0 * 64 + cgb;
            const float* bj = hin + (size_t)src  * 512 + r0 * 64 + cgb;
            float2 a0 = *(const float2*)(bi), a1 = *(const float2*)(bi + 4);
            float2 b0 = *(const float2*)(bj), b1 = *(const float2*)(bj + 4);
            pvi = make_float4(a0.x, a1.x, a0.y, a1.y);
            pvj = make_float4(b0.x, b1.x, b0.y, b1.y);
        }
    }

    for (int base = blockIdx.x * 4; base < EE; base += stride4) {
        const bool valid = pv;
        const int  tgt = ptgt;
        const float ic = pic;

        // ---- P0: commit prefetched gather to smem (permuted layout) ----
        if (valid) {
            *(float4*)(xc + r0 * PITCH + ppos) = pvi;
            *(float4*)(xs + r0 * PITCH + ppos) = pvj;
        }
        SUBBAR();

        // ---- prefetch next iteration ----
        {
            int en = base + stride4 + sub;
            pv = en < EE;
            if (pv) {
                int src = is64 ? ei[2 * en]        : ei[en];
                ptgt    = is64 ? ei[2 * (EE + en)] : ei[EE + en];
                pic = g_inv[ptgt];
                const float* bi = hin + (size_t)ptgt * 512 + r0 * 64 + cgb;
                const float* bj = hin + (size_t)src  * 512 + r0 * 64 + cgb;
                float2 a0 = *(const float2*)(bi), a1 = *(const float2*)(bi + 4);
                float2 b0 = *(const float2*)(bj), b1 = *(const float2*)(bj + 4);
                pvi = make_float4(a0.x, a1.x, a0.y, a1.y);
                pvj = make_float4(b0.x, b1.x, b0.y, b1.y);
            }
        }

        // ---- P1: bproj -> xc rows 8..15 ----
        if (valid) {
            unsigned a[8][4];
            load_a(a, xs, PITCH, lane);
            gemm_tile<0, true>(a, s_bw, s_b + 640, warp * 16,     xc + 8 * PITCH, PITCH, 0, 0, lane);
            gemm_tile<0, true>(a, s_bw, s_b + 640, warp * 16 + 8, xc + 8 * PITCH, PITCH, 0, 0, lane);
        }
        SUBBAR();

        // ---- P2: qkv ; q/k stored permuted, V transposed into vT (rows = permuted d) ----
        if (valid) {
            unsigned a[8][4];
            load_a(a, xc, PITCH, lane);
            #pragma unroll
            for (int nt = 0; nt < 6; nt++) {
                int jb = warp * 48 + nt * 8;
                float2 bb = *(const float2*)(s_b + jb + 2 * tg);
                float c0 = bb.x, c1 = bb.y, c2 = bb.x, c3 = bb.y;
                const float* wr = s_ipw + (jb + g) * PITCH;
                #pragma unroll
                for (int kb = 0; kb < 8; kb++) {
                    float2 w2 = *(const float2*)(wr + kb * 8 + 2 * tg);
                    mma_tf32(c0, c1, c2, c3, a[kb][0], a[kb][1], a[kb][2], a[kb][3],
                             __float_as_uint(w2.x), __float_as_uint(w2.y));
                }
                if (jb < 128) {
                    int p0 = jb + ((tg & 1) << 2) + (tg >> 1);
                    qv[g * QPITCH + p0]           = c0;
                    qv[g * QPITCH + p0 + 2]       = c1;
                    qv[(g + 8) * QPITCH + p0]     = c2;
                    qv[(g + 8) * QPITCH + p0 + 2] = c3;
                } else {
                    // vT row = permuted position of d within head
                    int dL = jb - 128 + 2 * tg;
                    float* vt = qv + 128 + 16 * (dL >> 4);
                    int d0 = dL & 15, d1 = (dL + 1) & 15;
                    int r0v = (d0 & 8) | ((d0 & 3) << 1) | ((d0 >> 2) & 1);
                    int r1v = (d1 & 8) | ((d1 & 3) << 1) | ((d1 >> 2) & 1);
                    vt[r0v * QPITCH + g]     = c0;
                    vt[r1v * QPITCH + g]     = c1;
                    vt[r0v * QPITCH + g + 8] = c2;
                    vt[r1v * QPITCH + g + 8] = c3;
                }
            }
        }
        SUBBAR();

        // ---- P3: attention via MMA (warp = head) ----
        if (valid) {
            const float* qb  = qv + warp * 16;
            const float* kbp = qv + 64 + warp * 16;
            // A = Q fragments (d permuted -> float2 pair loads)
            unsigned aq[2][4];
            #pragma unroll
            for (int kc = 0; kc < 2; kc++) {
                float2 u0 = *(const float2*)(qb + g * QPITCH + kc * 8 + 2 * tg);
                float2 u1 = *(const float2*)(qb + (g + 8) * QPITCH + kc * 8 + 2 * tg);
                aq[kc][0] = f2tf(u0.x); aq[kc][2] = f2tf(u0.y);
                aq[kc][1] = f2tf(u1.x); aq[kc][3] = f2tf(u1.y);
            }
            float s00, s01, s02, s03, s10, s11, s12, s13;
            {
                float c0 = 0, c1 = 0, c2 = 0, c3 = 0;
                #pragma unroll
                for (int kc = 0; kc < 2; kc++) {
                    float2 k2 = *(const float2*)(kbp + g * QPITCH + kc * 8 + 2 * tg);
                    mma_tf32(c0, c1, c2, c3, aq[kc][0], aq[kc][1], aq[kc][2], aq[kc][3],
                             f2tf(k2.x), f2tf(k2.y));
                }
                s00 = c0; s01 = c1; s02 = c2; s03 = c3;
            }
            {
                float c0 = 0, c1 = 0, c2 = 0, c3 = 0;
                #pragma unroll
                for (int kc = 0; kc < 2; kc++) {
                    float2 k2 = *(const float2*)(kbp + (8 + g) * QPITCH + kc * 8 + 2 * tg);
                    mma_tf32(c0, c1, c2, c3, aq[kc][0], aq[kc][1], aq[kc][2], aq[kc][3],
                             f2tf(k2.x), f2tf(k2.y));
                }
                s10 = c0; s11 = c1; s12 = c2; s13 = c3;
            }
            s00 *= 0.25f; s01 *= 0.25f; s02 *= 0.25f; s03 *= 0.25f;
            s10 *= 0.25f; s11 *= 0.25f; s12 *= 0.25f; s13 *= 0.25f;
            float m0 = fmaxf(fmaxf(s00, s01), fmaxf(s10, s11));
            float m1 = fmaxf(fmaxf(s02, s03), fmaxf(s12, s13));
            m0 = fmaxf(m0, __shfl_xor_sync(0xffffffffu, m0, 1));
            m0 = fmaxf(m0, __shfl_xor_sync(0xffffffffu, m0, 2));
            m1 = fmaxf(m1, __shfl_xor_sync(0xffffffffu, m1, 1));
            m1 = fmaxf(m1, __shfl_xor_sync(0xffffffffu, m1, 2));
            float e00 = __expf(s00 - m0), e01 = __expf(s01 - m0);
            float e10 = __expf(s10 - m0), e11 = __expf(s11 - m0);
            float e02 = __expf(s02 - m1), e03 = __expf(s03 - m1);
            float e12 = __expf(s12 - m1), e13 = __expf(s13 - m1);
            float t0 = (e00 + e01) + (e10 + e11);
            float t1 = (e02 + e03) + (e12 + e13);
            t0 += __shfl_xor_sync(0xffffffffu, t0, 1);
            t0 += __shfl_xor_sync(0xffffffffu, t0, 2);
            t1 += __shfl_xor_sync(0xffffffffu, t1, 1);
            t1 += __shfl_xor_sync(0xffffffffu, t1, 2);
            float r0s = 1.f / t0, r1s = 1.f / t1;
            // P stored at actual key columns (unpermuted keys)
            float* pb = ao + warp * 16;
            *(float2*)(pb + g * PITCH + 2 * tg)           = make_float2(e00 * r0s, e01 * r0s);
            *(float2*)(pb + g * PITCH + 8 + 2 * tg)       = make_float2(e10 * r0s, e11 * r0s);
            *(float2*)(pb + (g + 8) * PITCH + 2 * tg)     = make_float2(e02 * r1s, e03 * r1s);
            *(float2*)(pb + (g + 8) * PITCH + 8 + 2 * tg) = make_float2(e12 * r1s, e13 * r1s);
            __syncwarp();
            // reload P as A fragments (keys unpermuted -> scalar pairs)
            unsigned ap[2][4];
            #pragma unroll
            for (int kc = 0; kc < 2; kc++) {
                const float* p0 = pb + g * PITCH + kc * 8 + tg;
                const float* p1 = pb + (g + 8) * PITCH + kc * 8 + tg;
                ap[kc][0] = f2tf(p0[0]); ap[kc][1] = f2tf(p1[0]);
                ap[kc][2] = f2tf(p0[4]); ap[kc][3] = f2tf(p1[4]);
            }
            __syncwarp();
            // AV: B = vT (rows = permuted d positions, cols = keys unpermuted)
            const float* vtb = qv + 128 + 16 * warp;
            #pragma unroll
            for (int jb2 = 0; jb2 < 2; jb2++) {
                float c0 = 0, c1 = 0, c2 = 0, c3 = 0;
                #pragma unroll
                for (int kc = 0; kc < 2; kc++) {
                    const float* vr = vtb + (jb2 * 8 + g) * QPITCH + kc * 8;
                    mma_tf32(c0, c1, c2, c3, ap[kc][0], ap[kc][1], ap[kc][2], ap[kc][3],
                             f2tf(vr[tg]), f2tf(vr[tg + 4]));
                }
                // n-index = vT row = permuted position -> contiguous float2 store
                *(float2*)(ao + g * PITCH + warp * 16 + jb2 * 8 + 2 * tg)       = make_float2(c0, c1);
                *(float2*)(ao + (g + 8) * PITCH + warp * 16 + jb2 * 8 + 2 * tg) = make_float2(c2, c3);
            }
        }
        SUBBAR();

        // ---- P4: out_proj + residual -> qv ----
        if (valid) {
            unsigned a[8][4];
            load_a(a, ao, PITCH, lane);
            gemm_tile<2, false>(a, s_opw, s_b + 192, warp * 16,     qv, QPITCH, xc, PITCH, lane);
            gemm_tile<2, false>(a, s_opw, s_b + 192, warp * 16 + 8, qv, QPITCH, xc, PITCH, lane);
        }
        SUBBAR();

        // ---- LN1 (8 threads/row; position space, permuted gamma/beta) -> xc ----
        if (valid) {
            int row = st >> 3, part = st & 7, c0i = part * 8;
            const float4* p = (const float4*)(qv + row * QPITCH + c0i);
            float4 u0 = p[0], u1 = p[1];
            float s = (u0.x + u0.y) + (u0.z + u0.w) + (u1.x + u1.y) + (u1.z + u1.w);
            s += __shfl_xor_sync(0xffffffffu, s, 1);
            s += __shfl_xor_sync(0xffffffffu, s, 2);
            s += __shfl_xor_sync(0xffffffffu, s, 4);
            float mu = s * 0.015625f;
            float t0 = u0.x - mu, t1 = u0.y - mu, t2 = u0.z - mu, t3 = u0.w - mu;
            float t4 = u1.x - mu, t5 = u1.y - mu, t6 = u1.z - mu, t7 = u1.w - mu;
            float v = t0*t0 + t1*t1 + t2*t2 + t3*t3 + t4*t4 + t5*t5 + t6*t6 + t7*t7;
            v += __shfl_xor_sync(0xffffffffu, v, 1);
            v += __shfl_xor_sync(0xffffffffu, v, 2);
            v += __shfl_xor_sync(0xffffffffu, v, 4);
            float rstd = rsqrtf(v * 0.015625f + 1e-5f);
            const float4 g0 = *(const float4*)(s_b + 384 + c0i);
            const float4 g1 = *(const float4*)(s_b + 384 + c0i + 4);
            const float4 bb0 = *(const float4*)(s_b + 448 + c0i);
            const float4 bb1 = *(const float4*)(s_b + 448 + c0i + 4);
            float4 o0, o1;
            o0.x = t0 * rstd * g0.x + bb0.x; o0.y = t1 * rstd * g0.y + bb0.y;
            o0.z = t2 * rstd * g0.z + bb0.z; o0.w = t3 * rstd * g0.w + bb0.w;
            o1.x = t4 * rstd * g1.x + bb1.x; o1.y = t5 * rstd * g1.y + bb1.y;
            o1.z = t6 * rstd * g1.z + bb1.z; o1.w = t7 * rstd * g1.w + bb1.w;
            *(float4*)(xc + row * PITCH + c0i) = o0;
            *(float4*)(xc + row * PITCH + c0i + 4) = o1;
        }
        SUBBAR();

        // ---- P6: FF1 + relu -> ao ----
        if (valid) {
            unsigned a[8][4];
            load_a(a, xc, PITCH, lane);
            gemm_tile<1, false>(a, s_w1, s_b + 256, warp * 16,     ao, PITCH, 0, 0, lane);
            gemm_tile<1, false>(a, s_w1, s_b + 256, warp * 16 + 8, ao, PITCH, 0, 0, lane);
        }
        SUBBAR();

        // ---- P7: FF2 + residual -> qv ----
        if (valid) {
            unsigned a[8][4];
            load_a(a, ao, PITCH, lane);
            gemm_tile<2, false>(a, s_w2, s_b + 320, warp * 16,     qv, QPITCH, xc, PITCH, lane);
            gemm_tile<2, false>(a, s_w2, s_b + 320, warp * 16 + 8, qv, QPITCH, xc, PITCH, lane);
        }
        SUBBAR();

        // ---- LN2 (rows 0..7) + scaled vector-atomic scatter (de-permuted) ----
        if (valid) {
            int row = st >> 4, part = st & 15;
            int gc0 = part * 4;                           // global col base (contiguous 4)
            int pbase = (gc0 & ~7) + ((gc0 >> 2) & 1);    // position base; elements at +2*t
            const float* qr = qv + row * QPITCH + pbase;
            float v0 = qr[0], v1 = qr[2], v2 = qr[4], v3 = qr[6];
            float s = (v0 + v1) + (v2 + v3);
            s += __shfl_xor_sync(0xffffffffu, s, 1);
            s += __shfl_xor_sync(0xffffffffu, s, 2);
            s += __shfl_xor_sync(0xffffffffu, s, 4);
            s += __shfl_xor_sync(0xffffffffu, s, 8);
            float mu = s * 0.015625f;
            float t0 = v0 - mu, t1 = v1 - mu, t2 = v2 - mu, t3 = v3 - mu;
            float v = t0*t0 + t1*t1 + t2*t2 + t3*t3;
            v += __shfl_xor_sync(0xffffffffu, v, 1);
            v += __shfl_xor_sync(0xffffffffu, v, 2);
            v += __shfl_xor_sync(0xffffffffu, v, 4);
            v += __shfl_xor_sync(0xffffffffu, v, 8);
            float rstd = rsqrtf(v * 0.015625f + 1e-5f);
            const float4 gg = *(const float4*)(s_b + 512 + gc0);
            const float4 bb = *(const float4*)(s_b + 576 + gc0);
            float o0 = (t0 * rstd * gg.x + bb.x) * ic;
            float o1 = (t1 * rstd * gg.y + bb.y) * ic;
            float o2 = (t2 * rstd * gg.z + bb.z) * ic;
            float o3 = (t3 * rstd * gg.w + bb.w) * ic;
            float* dst = hout + (size_t)tgt * 512 + row * 64 + gc0;
            asm volatile("red.global.add.v4.f32 [%0], {%1,%2,%3,%4};"
                         :: "l"(dst), "f"(o0), "f"(o1), "f"(o2), "f"(o3) : "memory");
        }
        // no trailing barrier: next write to qv is P2 (two barriers away)
    }
}

// ---------------- output head ----------------
__global__ void out_kernel(const float* __restrict__ ow,
                           const float* __restrict__ ob,
                           float* __restrict__ out) {
    __shared__ float shs[8][64];
    int w = threadIdx.x >> 5, lane = threadIdx.x & 31;
    int n = blockIdx.x * 8 + w;
    if (n >= NN) return;
    const float* hr = g_hA + (size_t)n * 512;
    float lo = 0.f, hi = 0.f;
    #pragma unroll
    for (int c = 0; c < 8; c++) { lo += hr[c * 64 + lane]; hi += hr[c * 64 + 32 + lane]; }
    shs[w][lane] = lo; shs[w][lane + 32] = hi;
    __syncwarp();
    float z = -1e30f;
    if (lane < 16) {
        float acc = 8.f * ob[lane];
        const float* wr = ow + lane * 64;
        #pragma unroll
        for (int d = 0; d < 64; d++) acc = fmaf(shs[w][d], wr[d], acc);
        z = acc;
    }
    float m = z;
    #pragma unroll
    for (int off = 8; off; off >>= 1) m = fmaxf(m, __shfl_xor_sync(0xffffffffu, m, off, 16));
    float p = __expf(z - m);
    float s = p;
    #pragma unroll
    for (int off = 8; off; off >>= 1) s += __shfl_xor_sync(0xffffffffu, s, off, 16);
    if (lane < 16) out[n * 16 + lane] = p / s;
}

// ---------------- launch ----------------
extern "C" void kernel_launch(void* const* d_in, const int* in_sizes, int n_in,
                              void* d_out, int out_size) {
    const float* x    = (const float*)d_in[0];
    const int*   ei   = (const int*)d_in[1];
    const float* numw = (const float*)d_in[2];
    const float* numb = (const float*)d_in[3];
    const float* bpw  = (const float*)d_in[4];
    const float* bpb  = (const float*)d_in[5];
    const float* ipw  = (const float*)d_in[6];
    const float* ipb  = (const float*)d_in[7];
    const float* opw  = (const float*)d_in[8];
    const float* opb  = (const float*)d_in[9];
    const float* g1   = (const float*)d_in[10];
    const float* b1   = (const float*)d_in[11];
    const float* g2   = (const float*)d_in[12];
    const float* b2   = (const float*)d_in[13];
    const float* w1   = (const float*)d_in[14];
    const float* fb1  = (const float*)d_in[15];
    const float* w2   = (const float*)d_in[16];
    const float* fb2  = (const float*)d_in[17];
    const float* ow   = (const float*)d_in[18];
    const float* ob   = (const float*)d_in[19];
    float* out = (float*)d_out;

    const int SMEM_BYTES = (192 * PITCH + 4 * 64 * PITCH + 704 + 4 * 5888) * 4;
    cudaFuncSetAttribute(edge_kernel, cudaFuncAttributeMaxDynamicSharedMemorySize, SMEM_BYTES);

    int dev = 0, sms = 148;
    cudaGetDevice(&dev);
    cudaDeviceGetAttribute(&sms, cudaDevAttrMultiProcessorCount, dev);

    setup0_kernel<<<(NN * 128 + 255) / 256, 256>>>();
    detect_kernel<<<256, 256>>>(ei);
    embed_kernel<<<(NN * 512 + 255) / 256, 256>>>(x, numw, numb);
    count_kernel<<<(EE + 255) / 256, 256>>>(ei);
    fin_cnt_kernel<<<(NN + 255) / 256, 256>>>();

    // layer 0: A -> B
    edge_kernel<<<sms, 512, SMEM_BYTES>>>(ei, 0,
        bpw, bpb, ipw, ipb, opw, opb, g1, b1, g2, b2, w1, fb1, w2, fb2);

    // layer 1: B -> A
    zeroA_kernel<<<(NN * 128 + 255) / 256, 256>>>();
    edge_kernel<<<sms, 512, SMEM_BYTES>>>(ei, 1,
        bpw + 64 * 64, bpb + 64, ipw + 192 * 64, ipb + 192, opw + 64 * 64, opb + 64,
        g1 + 64, b1 + 64, g2 + 64, b2 + 64,
        w1 + 64 * 64, fb1 + 64, w2 + 64 * 64, fb2 + 64);

    out_kernel<<<(NN + 7) / 8, 256>>>(ow, ob, out);
}

// round 6
// speedup vs baseline: 1.4378x; 1.4378x over previous
#include <cuda_runtime.h>

#define NN 50000
#define CC 8
#define DD 64
#define EE 100000
#define PITCH 68      // activation pitch (conflict-free for scalar frag loads)
#define WPITCH 72     // weight pitch (conflict-free for float2 k-pair loads)
#define QPITCH 196    // padded row for qkv (192 cols)

// Weights stored k-permuted within each 8-block: position 2t holds col t,
// position 2t+1 holds col t+4  (t in 0..3). So a float2 at offset 2*tg yields
// exactly the MMA B-slot pair (k=tg, k=tg+4). Activations are NOT permuted.

// -------- scratch (device globals: allocation-free) --------
__device__ float g_hA[(size_t)NN * 512];
__device__ float g_hB[(size_t)NN * 512];
__device__ float g_inv[NN];
__device__ int   g_any;

// ---------------- setup kernels ----------------

__global__ void setup0_kernel() {
    size_t i = (size_t)blockIdx.x * blockDim.x + threadIdx.x;
    if (i == 0) g_any = 0;
    if (i < NN) g_inv[i] = 0.f;
    if (i < (size_t)NN * 128) ((float4*)g_hB)[i] = make_float4(0.f, 0.f, 0.f, 0.f);
}

__global__ void detect_kernel(const int* __restrict__ ei) {
    int i = blockIdx.x * blockDim.x + threadIdx.x;
    int v = 0;
    for (int k = i; k < EE; k += gridDim.x * blockDim.x) v |= ei[2 * k + 1];
    if (v) atomicOr(&g_any, 1);
}

__global__ void embed_kernel(const float* __restrict__ x,
                             const float* __restrict__ nw,
                             const float* __restrict__ nb) {
    int i = blockIdx.x * blockDim.x + threadIdx.x;
    if (i < NN * 512) {
        int n = i >> 9;
        int r = i & 511;
        g_hA[i] = x[n * 8 + (r >> 6)] * nw[r] + nb[r];
    }
}

__global__ void count_kernel(const int* __restrict__ ei) {
    int e = blockIdx.x * blockDim.x + threadIdx.x;
    if (e < EE) {
        int is64 = (g_any == 0);
        int t = is64 ? ei[2 * (EE + e)] : ei[EE + e];
        atomicAdd(&g_inv[t], 1.0f);
    }
}

__global__ void fin_cnt_kernel() {
    int i = blockIdx.x * blockDim.x + threadIdx.x;
    if (i < NN) g_inv[i] = 1.0f / fmaxf(g_inv[i], 1.0f);
}

__global__ void zeroA_kernel() {
    size_t i = (size_t)blockIdx.x * blockDim.x + threadIdx.x;
    if (i < (size_t)NN * 128) ((float4*)g_hA)[i] = make_float4(0.f, 0.f, 0.f, 0.f);
}

// ---------------- tf32 mma helpers ----------------

__device__ __forceinline__ unsigned f2tf(float x) {
    unsigned r;
    asm("cvt.rna.tf32.f32 %0, %1;" : "=r"(r) : "f"(x));
    return r;
}

__device__ __forceinline__ void mma_tf32(float& c0, float& c1, float& c2, float& c3,
                                         unsigned a0, unsigned a1, unsigned a2, unsigned a3,
                                         unsigned b0, unsigned b1) {
    asm volatile(
        "mma.sync.aligned.m16n8k8.row.col.f32.tf32.tf32.f32 "
        "{%0,%1,%2,%3}, {%4,%5,%6,%7}, {%8,%9}, {%0,%1,%2,%3};\n"
        : "+f"(c0), "+f"(c1), "+f"(c2), "+f"(c3)
        : "r"(a0), "r"(a1), "r"(a2), "r"(a3), "r"(b0), "r"(b1));
}

// A-fragment load from UNPERMUTED activations (scalar, conflict-free banks)
__device__ __forceinline__ void load_a(unsigned a[8][4], const float* __restrict__ X,
                                       int xp, int lane) {
    int row = lane >> 2, kc = lane & 3;
    const float* p0 = X + row * xp + kc;
    const float* p1 = X + (row + 8) * xp + kc;
    #pragma unroll
    for (int kb = 0; kb < 8; kb++) {
        a[kb][0] = f2tf(p0[kb * 8]);
        a[kb][1] = f2tf(p1[kb * 8]);
        a[kb][2] = f2tf(p0[kb * 8 + 4]);
        a[kb][3] = f2tf(p1[kb * 8 + 4]);
    }
}

// EPI: 0 plain, 1 relu, 2 add residual R ; ROWS8: only rows 0..7 stored
// W is in k-permuted layout with pitch WPITCH; everything else unpermuted.
template<int EPI, bool ROWS8>
__device__ __forceinline__ void gemm_tile(const unsigned a[8][4],
                                          const float* __restrict__ W,
                                          const float* __restrict__ bias,
                                          int jbase,
                                          float* __restrict__ C, int cp,
                                          const float* __restrict__ R, int rp,
                                          int lane) {
    int g = lane >> 2, tg = lane & 3;
    int col0 = jbase + 2 * tg;
    float2 bb = *(const float2*)(bias + col0);
    float c0 = bb.x, c1 = bb.y, c2 = bb.x, c3 = bb.y;
    const float* wr = W + (jbase + g) * WPITCH;
    #pragma unroll
    for (int kb = 0; kb < 8; kb++) {
        float2 w2 = *(const float2*)(wr + kb * 8 + 2 * tg);   // (col tg, col tg+4)
        mma_tf32(c0, c1, c2, c3, a[kb][0], a[kb][1], a[kb][2], a[kb][3],
                 __float_as_uint(w2.x), __float_as_uint(w2.y));
    }
    if (EPI == 2) {
        float2 r0 = *(const float2*)(R + g * rp + col0);
        float2 r1 = *(const float2*)(R + (g + 8) * rp + col0);
        c0 += r0.x; c1 += r0.y; c2 += r1.x; c3 += r1.y;
    }
    if (EPI == 1) {
        c0 = fmaxf(c0, 0.f); c1 = fmaxf(c1, 0.f);
        c2 = fmaxf(c2, 0.f); c3 = fmaxf(c3, 0.f);
    }
    *(float2*)(C + g * cp + col0) = make_float2(c0, c1);
    if (!ROWS8) *(float2*)(C + (g + 8) * cp + col0) = make_float2(c2, c3);
}

// ---------------- main per-edge transformer kernel ----------------

#define SUBBAR() asm volatile("bar.sync %0, 128;" :: "r"(sub + 1) : "memory")

__global__ void __launch_bounds__(512, 1)
edge_kernel(const int* __restrict__ ei, int dir,
            const float* __restrict__ bpw, const float* __restrict__ bpb,
            const float* __restrict__ ipw, const float* __restrict__ ipb,
            const float* __restrict__ opw, const float* __restrict__ opb,
            const float* __restrict__ ln1g, const float* __restrict__ ln1b,
            const float* __restrict__ ln2g, const float* __restrict__ ln2b,
            const float* __restrict__ w1,  const float* __restrict__ fb1,
            const float* __restrict__ w2,  const float* __restrict__ fb2) {
    extern __shared__ float sm[];
    float* s_ipw = sm;                          // 192*72
    float* s_opw = s_ipw + 192 * WPITCH;
    float* s_w1  = s_opw + 64 * WPITCH;
    float* s_w2  = s_w1  + 64 * WPITCH;
    float* s_bw  = s_w2  + 64 * WPITCH;
    float* s_b   = s_bw  + 64 * WPITCH;         // 704 floats biases/ln
    float* s_act = s_b + 704;

    const float* hin  = dir ? g_hB : g_hA;
    float*       hout = dir ? g_hA : g_hB;

    const int tid = threadIdx.x;

    // ---- stage weights once: tf32-rounded, k-dim permuted, pitch 72 ----
    for (int i = tid; i < 192 * 64; i += 512) {
        int j = i >> 6, k = i & 63;
        int kp = (k & 56) | ((k & 3) << 1) | ((k >> 2) & 1);
        s_ipw[j * WPITCH + kp] = __uint_as_float(f2tf(ipw[i]));
    }
    for (int i = tid; i < 64 * 64; i += 512) {
        int j = i >> 6, k = i & 63;
        int kp = (k & 56) | ((k & 3) << 1) | ((k >> 2) & 1);
        int r = j * WPITCH + kp;
        s_opw[r] = __uint_as_float(f2tf(opw[i]));
        s_w1[r]  = __uint_as_float(f2tf(w1[i]));
        s_w2[r]  = __uint_as_float(f2tf(w2[i]));
        s_bw[r]  = __uint_as_float(f2tf(bpw[i]));
    }
    for (int i = tid; i < 192; i += 512) s_b[i] = ipb[i];
    if (tid < 64) {
        s_b[192 + tid] = opb[tid];  s_b[256 + tid] = fb1[tid];
        s_b[320 + tid] = fb2[tid];  s_b[384 + tid] = ln1g[tid];
        s_b[448 + tid] = ln1b[tid]; s_b[512 + tid] = ln2g[tid];
        s_b[576 + tid] = ln2b[tid]; s_b[640 + tid] = bpb[tid];
    }
    __syncthreads();

    const int sub  = tid >> 7;     // 0..3 edge slot
    const int st   = tid & 127;
    const int warp = st >> 5;
    const int lane = st & 31;
    const int g    = lane >> 2, tg = lane & 3;
    float* xs  = s_act + sub * 5888;       // 8*68
    float* xc  = xs + 8 * PITCH;           // 16*68
    float* qv  = xc + 16 * PITCH;          // 16*196 (q 0..63 | k 64..127 | vT 128..191)
    float* ao  = qv + 16 * QPITCH;         // 16*68  (P scratch / attn out / ff hidden)

    const int is64 = (g_any == 0);
    const int r0 = st >> 4, d0 = (st & 15) << 2;
    const int stride4 = gridDim.x * 4;

    // ---- prologue prefetch ----
    bool pv; int ptgt = 0; float pic = 0.f;
    float4 pvi = make_float4(0, 0, 0, 0), pvj = pvi;
    {
        int e = blockIdx.x * 4 + sub;
        pv = e < EE;
        if (pv) {
            int src = is64 ? ei[2 * e]        : ei[e];
            ptgt    = is64 ? ei[2 * (EE + e)] : ei[EE + e];
            pic = g_inv[ptgt];
            pvi = *(const float4*)(hin + (size_t)ptgt * 512 + r0 * 64 + d0);
            pvj = *(const float4*)(hin + (size_t)src  * 512 + r0 * 64 + d0);
        }
    }

    for (int base = blockIdx.x * 4; base < EE; base += stride4) {
        const bool valid = pv;
        const int  tgt = ptgt;
        const float ic = pic;

        // ---- P0: commit prefetched gather to smem ----
        if (valid) {
            *(float4*)(xc + r0 * PITCH + d0) = pvi;
            *(float4*)(xs + r0 * PITCH + d0) = pvj;
        }
        SUBBAR();

        // ---- prefetch next iteration ----
        {
            int en = base + stride4 + sub;
            pv = en < EE;
            if (pv) {
                int src = is64 ? ei[2 * en]        : ei[en];
                ptgt    = is64 ? ei[2 * (EE + en)] : ei[EE + en];
                pic = g_inv[ptgt];
                pvi = *(const float4*)(hin + (size_t)ptgt * 512 + r0 * 64 + d0);
                pvj = *(const float4*)(hin + (size_t)src  * 512 + r0 * 64 + d0);
            }
        }

        // ---- P1: bproj -> xc rows 8..15 ----
        if (valid) {
            unsigned a[8][4];
            load_a(a, xs, PITCH, lane);
            gemm_tile<0, true>(a, s_bw, s_b + 640, warp * 16,     xc + 8 * PITCH, PITCH, 0, 0, lane);
            gemm_tile<0, true>(a, s_bw, s_b + 640, warp * 16 + 8, xc + 8 * PITCH, PITCH, 0, 0, lane);
        }
        SUBBAR();

        // ---- P2: qkv ; V stored transposed per head into vT region ----
        if (valid) {
            unsigned a[8][4];
            load_a(a, xc, PITCH, lane);
            #pragma unroll
            for (int nt = 0; nt < 6; nt++) {
                int jb = warp * 48 + nt * 8;
                float2 bb = *(const float2*)(s_b + jb + 2 * tg);
                float c0 = bb.x, c1 = bb.y, c2 = bb.x, c3 = bb.y;
                const float* wr = s_ipw + (jb + g) * WPITCH;
                #pragma unroll
                for (int kb = 0; kb < 8; kb++) {
                    float2 w2 = *(const float2*)(wr + kb * 8 + 2 * tg);
                    mma_tf32(c0, c1, c2, c3, a[kb][0], a[kb][1], a[kb][2], a[kb][3],
                             __float_as_uint(w2.x), __float_as_uint(w2.y));
                }
                if (jb < 128) {
                    *(float2*)(qv + g * QPITCH + jb + 2 * tg)       = make_float2(c0, c1);
                    *(float2*)(qv + (g + 8) * QPITCH + jb + 2 * tg) = make_float2(c2, c3);
                } else {
                    // transposed V store: vT[d][key] at qv[d&15][128 + 16*(d>>4) + key]
                    int dL = jb - 128 + 2 * tg;
                    float* vt = qv + 128 + 16 * (dL >> 4);
                    int dd = dL & 15;
                    vt[dd * QPITCH + g]           = c0;
                    vt[(dd + 1) * QPITCH + g]     = c1;
                    vt[dd * QPITCH + g + 8]       = c2;
                    vt[(dd + 1) * QPITCH + g + 8] = c3;
                }
            }
        }
        SUBBAR();

        // ---- P3: attention via MMA (warp = head) ----
        if (valid) {
            const float* qb  = qv + warp * 16;
            const float* kbp = qv + 64 + warp * 16;
            unsigned aq[2][4];
            #pragma unroll
            for (int kc = 0; kc < 2; kc++) {
                const float* p0 = qb + g * QPITCH + kc * 8 + tg;
                const float* p1 = qb + (g + 8) * QPITCH + kc * 8 + tg;
                aq[kc][0] = f2tf(p0[0]); aq[kc][1] = f2tf(p1[0]);
                aq[kc][2] = f2tf(p0[4]); aq[kc][3] = f2tf(p1[4]);
            }
            float s00, s01, s02, s03, s10, s11, s12, s13;
            {
                float c0 = 0, c1 = 0, c2 = 0, c3 = 0;
                #pragma unroll
                for (int kc = 0; kc < 2; kc++) {
                    const float* kr = kbp + g * QPITCH + kc * 8;
                    mma_tf32(c0, c1, c2, c3, aq[kc][0], aq[kc][1], aq[kc][2], aq[kc][3],
                             f2tf(kr[tg]), f2tf(kr[tg + 4]));
                }
                s00 = c0; s01 = c1; s02 = c2; s03 = c3;
            }
            {
                float c0 = 0, c1 = 0, c2 = 0, c3 = 0;
                #pragma unroll
                for (int kc = 0; kc < 2; kc++) {
                    const float* kr = kbp + (8 + g) * QPITCH + kc * 8;
                    mma_tf32(c0, c1, c2, c3, aq[kc][0], aq[kc][1], aq[kc][2], aq[kc][3],
                             f2tf(kr[tg]), f2tf(kr[tg + 4]));
                }
                s10 = c0; s11 = c1; s12 = c2; s13 = c3;
            }
            s00 *= 0.25f; s01 *= 0.25f; s02 *= 0.25f; s03 *= 0.25f;
            s10 *= 0.25f; s11 *= 0.25f; s12 *= 0.25f; s13 *= 0.25f;
            float m0 = fmaxf(fmaxf(s00, s01), fmaxf(s10, s11));
            float m1 = fmaxf(fmaxf(s02, s03), fmaxf(s12, s13));
            m0 = fmaxf(m0, __shfl_xor_sync(0xffffffffu, m0, 1));
            m0 = fmaxf(m0, __shfl_xor_sync(0xffffffffu, m0, 2));
            m1 = fmaxf(m1, __shfl_xor_sync(0xffffffffu, m1, 1));
            m1 = fmaxf(m1, __shfl_xor_sync(0xffffffffu, m1, 2));
            float e00 = __expf(s00 - m0), e01 = __expf(s01 - m0);
            float e10 = __expf(s10 - m0), e11 = __expf(s11 - m0);
            float e02 = __expf(s02 - m1), e03 = __expf(s03 - m1);
            float e12 = __expf(s12 - m1), e13 = __expf(s13 - m1);
            float t0 = (e00 + e01) + (e10 + e11);
            float t1 = (e02 + e03) + (e12 + e13);
            t0 += __shfl_xor_sync(0xffffffffu, t0, 1);
            t0 += __shfl_xor_sync(0xffffffffu, t0, 2);
            t1 += __shfl_xor_sync(0xffffffffu, t1, 1);
            t1 += __shfl_xor_sync(0xffffffffu, t1, 2);
            float r0s = 1.f / t0, r1s = 1.f / t1;
            float* pb = ao + warp * 16;
            *(float2*)(pb + g * PITCH + 2 * tg)           = make_float2(e00 * r0s, e01 * r0s);
            *(float2*)(pb + g * PITCH + 8 + 2 * tg)       = make_float2(e10 * r0s, e11 * r0s);
            *(float2*)(pb + (g + 8) * PITCH + 2 * tg)     = make_float2(e02 * r1s, e03 * r1s);
            *(float2*)(pb + (g + 8) * PITCH + 8 + 2 * tg) = make_float2(e12 * r1s, e13 * r1s);
            __syncwarp();
            unsigned ap[2][4];
            #pragma unroll
            for (int kc = 0; kc < 2; kc++) {
                const float* p0 = pb + g * PITCH + kc * 8 + tg;
                const float* p1 = pb + (g + 8) * PITCH + kc * 8 + tg;
                ap[kc][0] = f2tf(p0[0]); ap[kc][1] = f2tf(p1[0]);
                ap[kc][2] = f2tf(p0[4]); ap[kc][3] = f2tf(p1[4]);
            }
            __syncwarp();
            const float* vtb = qv + 128 + 16 * warp;
            #pragma unroll
            for (int jb2 = 0; jb2 < 2; jb2++) {
                float c0 = 0, c1 = 0, c2 = 0, c3 = 0;
                #pragma unroll
                for (int kc = 0; kc < 2; kc++) {
                    const float* vr = vtb + (jb2 * 8 + g) * QPITCH + kc * 8;
                    mma_tf32(c0, c1, c2, c3, ap[kc][0], ap[kc][1], ap[kc][2], ap[kc][3],
                             f2tf(vr[tg]), f2tf(vr[tg + 4]));
                }
                *(float2*)(ao + g * PITCH + warp * 16 + jb2 * 8 + 2 * tg)       = make_float2(c0, c1);
                *(float2*)(ao + (g + 8) * PITCH + warp * 16 + jb2 * 8 + 2 * tg) = make_float2(c2, c3);
            }
        }
        SUBBAR();

        // ---- P4: out_proj + residual -> qv ----
        if (valid) {
            unsigned a[8][4];
            load_a(a, ao, PITCH, lane);
            gemm_tile<2, false>(a, s_opw, s_b + 192, warp * 16,     qv, QPITCH, xc, PITCH, lane);
            gemm_tile<2, false>(a, s_opw, s_b + 192, warp * 16 + 8, qv, QPITCH, xc, PITCH, lane);
        }
        SUBBAR();

        // ---- LN1 (8 threads/row) -> xc ----
        if (valid) {
            int row = st >> 3, part = st & 7, c0i = part * 8;
            const float4* p = (const float4*)(qv + row * QPITCH + c0i);
            float4 u0 = p[0], u1 = p[1];
            float s = (u0.x + u0.y) + (u0.z + u0.w) + (u1.x + u1.y) + (u1.z + u1.w);
            s += __shfl_xor_sync(0xffffffffu, s, 1);
            s += __shfl_xor_sync(0xffffffffu, s, 2);
            s += __shfl_xor_sync(0xffffffffu, s, 4);
            float mu = s * 0.015625f;
            float t0 = u0.x - mu, t1 = u0.y - mu, t2 = u0.z - mu, t3 = u0.w - mu;
            float t4 = u1.x - mu, t5 = u1.y - mu, t6 = u1.z - mu, t7 = u1.w - mu;
            float v = t0*t0 + t1*t1 + t2*t2 + t3*t3 + t4*t4 + t5*t5 + t6*t6 + t7*t7;
            v += __shfl_xor_sync(0xffffffffu, v, 1);
            v += __shfl_xor_sync(0xffffffffu, v, 2);
            v += __shfl_xor_sync(0xffffffffu, v, 4);
            float rstd = rsqrtf(v * 0.015625f + 1e-5f);
            const float4 g0 = *(const float4*)(s_b + 384 + c0i);
            const float4 g1 = *(const float4*)(s_b + 384 + c0i + 4);
            const float4 bb0 = *(const float4*)(s_b + 448 + c0i);
            const float4 bb1 = *(const float4*)(s_b + 448 + c0i + 4);
            float4 o0, o1;
            o0.x = t0 * rstd * g0.x + bb0.x; o0.y = t1 * rstd * g0.y + bb0.y;
            o0.z = t2 * rstd * g0.z + bb0.z; o0.w = t3 * rstd * g0.w + bb0.w;
            o1.x = t4 * rstd * g1.x + bb1.x; o1.y = t5 * rstd * g1.y + bb1.y;
            o1.z = t6 * rstd * g1.z + bb1.z; o1.w = t7 * rstd * g1.w + bb1.w;
            *(float4*)(xc + row * PITCH + c0i) = o0;
            *(float4*)(xc + row * PITCH + c0i + 4) = o1;
        }
        SUBBAR();

        // ---- P6: FF1 + relu -> ao ----
        if (valid) {
            unsigned a[8][4];
            load_a(a, xc, PITCH, lane);
            gemm_tile<1, false>(a, s_w1, s_b + 256, warp * 16,     ao, PITCH, 0, 0, lane);
            gemm_tile<1, false>(a, s_w1, s_b + 256, warp * 16 + 8, ao, PITCH, 0, 0, lane);
        }
        SUBBAR();

        // ---- P7: FF2 + residual -> qv ----
        if (valid) {
            unsigned a[8][4];
            load_a(a, ao, PITCH, lane);
            gemm_tile<2, false>(a, s_w2, s_b + 320, warp * 16,     qv, QPITCH, xc, PITCH, lane);
            gemm_tile<2, false>(a, s_w2, s_b + 320, warp * 16 + 8, qv, QPITCH, xc, PITCH, lane);
        }
        SUBBAR();

        // ---- LN2 (rows 0..7) + scaled vector-atomic scatter ----
        if (valid) {
            int row = st >> 4, part = st & 15, c0i = part * 4;
            float4 u = *(const float4*)(qv + row * QPITCH + c0i);
            float s = (u.x + u.y) + (u.z + u.w);
            s += __shfl_xor_sync(0xffffffffu, s, 1);
            s += __shfl_xor_sync(0xffffffffu, s, 2);
            s += __shfl_xor_sync(0xffffffffu, s, 4);
            s += __shfl_xor_sync(0xffffffffu, s, 8);
            float mu = s * 0.015625f;
            float t0 = u.x - mu, t1 = u.y - mu, t2 = u.z - mu, t3 = u.w - mu;
            float v = t0*t0 + t1*t1 + t2*t2 + t3*t3;
            v += __shfl_xor_sync(0xffffffffu, v, 1);
            v += __shfl_xor_sync(0xffffffffu, v, 2);
            v += __shfl_xor_sync(0xffffffffu, v, 4);
            v += __shfl_xor_sync(0xffffffffu, v, 8);
            float rstd = rsqrtf(v * 0.015625f + 1e-5f);
            const float4 gg = *(const float4*)(s_b + 512 + c0i);
            const float4 bb = *(const float4*)(s_b + 576 + c0i);
            float o0 = (t0 * rstd * gg.x + bb.x) * ic;
            float o1 = (t1 * rstd * gg.y + bb.y) * ic;
            float o2 = (t2 * rstd * gg.z + bb.z) * ic;
            float o3 = (t3 * rstd * gg.w + bb.w) * ic;
            float* dst = hout + (size_t)tgt * 512 + row * 64 + c0i;
            asm volatile("red.global.add.v4.f32 [%0], {%1,%2,%3,%4};"
                         :: "l"(dst), "f"(o0), "f"(o1), "f"(o2), "f"(o3) : "memory");
        }
        // no trailing barrier: next write to qv is P2 (two barriers away)
    }
}

// ---------------- output head ----------------
__global__ void out_kernel(const float* __restrict__ ow,
                           const float* __restrict__ ob,
                           float* __restrict__ out) {
    __shared__ float shs[8][64];
    int w = threadIdx.x >> 5, lane = threadIdx.x & 31;
    int n = blockIdx.x * 8 + w;
    if (n >= NN) return;
    const float* hr = g_hA + (size_t)n * 512;
    float lo = 0.f, hi = 0.f;
    #pragma unroll
    for (int c = 0; c < 8; c++) { lo += hr[c * 64 + lane]; hi += hr[c * 64 + 32 + lane]; }
    shs[w][lane] = lo; shs[w][lane + 32] = hi;
    __syncwarp();
    float z = -1e30f;
    if (lane < 16) {
        float acc = 8.f * ob[lane];
        const float* wr = ow + lane * 64;
        #pragma unroll
        for (int d = 0; d < 64; d++) acc = fmaf(shs[w][d], wr[d], acc);
        z = acc;
    }
    float m = z;
    #pragma unroll
    for (int off = 8; off; off >>= 1) m = fmaxf(m, __shfl_xor_sync(0xffffffffu, m, off, 16));
    float p = __expf(z - m);
    float s = p;
    #pragma unroll
    for (int off = 8; off; off >>= 1) s += __shfl_xor_sync(0xffffffffu, s, off, 16);
    if (lane < 16) out[n * 16 + lane] = p / s;
}

// ---------------- launch ----------------
extern "C" void kernel_launch(void* const* d_in, const int* in_sizes, int n_in,
                              void* d_out, int out_size) {
    const float* x    = (const float*)d_in[0];
    const int*   ei   = (const int*)d_in[1];
    const float* numw = (const float*)d_in[2];
    const float* numb = (const float*)d_in[3];
    const float* bpw  = (const float*)d_in[4];
    const float* bpb  = (const float*)d_in[5];
    const float* ipw  = (const float*)d_in[6];
    const float* ipb  = (const float*)d_in[7];
    const float* opw  = (const float*)d_in[8];
    const float* opb  = (const float*)d_in[9];
    const float* g1   = (const float*)d_in[10];
    const float* b1   = (const float*)d_in[11];
    const float* g2   = (const float*)d_in[12];
    const float* b2   = (const float*)d_in[13];
    const float* w1   = (const float*)d_in[14];
    const float* fb1  = (const float*)d_in[15];
    const float* w2   = (const float*)d_in[16];
    const float* fb2  = (const float*)d_in[17];
    const float* ow   = (const float*)d_in[18];
    const float* ob   = (const float*)d_in[19];
    float* out = (float*)d_out;

    const int SMEM_BYTES = (192 * WPITCH + 4 * 64 * WPITCH + 704 + 4 * 5888) * 4;
    cudaFuncSetAttribute(edge_kernel, cudaFuncAttributeMaxDynamicSharedMemorySize, SMEM_BYTES);

    int dev = 0, sms = 148;
    cudaGetDevice(&dev);
    cudaDeviceGetAttribute(&sms, cudaDevAttrMultiProcessorCount, dev);

    setup0_kernel<<<(NN * 128 + 255) / 256, 256>>>();
    detect_kernel<<<256, 256>>>(ei);
    embed_kernel<<<(NN * 512 + 255) / 256, 256>>>(x, numw, numb);
    count_kernel<<<(EE + 255) / 256, 256>>>(ei);
    fin_cnt_kernel<<<(NN + 255) / 256, 256>>>();

    // layer 0: A -> B
    edge_kernel<<<sms, 512, SMEM_BYTES>>>(ei, 0,
        bpw, bpb, ipw, ipb, opw, opb, g1, b1, g2, b2, w1, fb1, w2, fb2);

    // layer 1: B -> A
    zeroA_kernel<<<(NN * 128 + 255) / 256, 256>>>();
    edge_kernel<<<sms, 512, SMEM_BYTES>>>(ei, 1,
        bpw + 64 * 64, bpb + 64, ipw + 192 * 64, ipb + 192, opw + 64 * 64, opb + 64,
        g1 + 64, b1 + 64, g2 + 64, b2 + 64,
        w1 + 64 * 64, fb1 + 64, w2 + 64 * 64, fb2 + 64);

    out_kernel<<<(NN + 7) / 8, 256>>>(ow, ob, out);
}

// round 7
// speedup vs baseline: 1.4380x; 1.0002x over previous
#include <cuda_runtime.h>

#define NN 50000
#define CC 8
#define DD 64
#define EE 100000
#define PITCH 68      // activation pitch (conflict-free for scalar frag loads)
#define WPITCH 72     // weight pitch (conflict-free for float2 k-pair loads)
#define QPITCH 196    // padded row for qkv (192 cols)

// Weights stored k-permuted within each 8-block: position 2t holds col t,
// position 2t+1 holds col t+4  (t in 0..3). So a float2 at offset 2*tg yields
// exactly the MMA B-slot pair (k=tg, k=tg+4). Activations are NOT permuted.

// -------- scratch (device globals: allocation-free) --------
__device__ float g_hA[(size_t)NN * 512];
__device__ float g_hB[(size_t)NN * 512];
__device__ float g_inv[NN];
__device__ int   g_any;

// ---------------- setup kernels ----------------

__global__ void setup0_kernel() {
    size_t i = (size_t)blockIdx.x * blockDim.x + threadIdx.x;
    if (i == 0) g_any = 0;
    if (i < NN) g_inv[i] = 0.f;
    if (i < (size_t)NN * 128) ((float4*)g_hB)[i] = make_float4(0.f, 0.f, 0.f, 0.f);
}

__global__ void detect_kernel(const int* __restrict__ ei) {
    int i = blockIdx.x * blockDim.x + threadIdx.x;
    int v = 0;
    for (int k = i; k < EE; k += gridDim.x * blockDim.x) v |= ei[2 * k + 1];
    if (v) atomicOr(&g_any, 1);
}

__global__ void embed_kernel(const float* __restrict__ x,
                             const float* __restrict__ nw,
                             const float* __restrict__ nb) {
    int i = blockIdx.x * blockDim.x + threadIdx.x;
    if (i < NN * 512) {
        int n = i >> 9;
        int r = i & 511;
        g_hA[i] = x[n * 8 + (r >> 6)] * nw[r] + nb[r];
    }
}

__global__ void count_kernel(const int* __restrict__ ei) {
    int e = blockIdx.x * blockDim.x + threadIdx.x;
    if (e < EE) {
        int is64 = (g_any == 0);
        int t = is64 ? ei[2 * (EE + e)] : ei[EE + e];
        atomicAdd(&g_inv[t], 1.0f);
    }
}

__global__ void fin_cnt_kernel() {
    int i = blockIdx.x * blockDim.x + threadIdx.x;
    if (i < NN) g_inv[i] = 1.0f / fmaxf(g_inv[i], 1.0f);
}

__global__ void zeroA_kernel() {
    size_t i = (size_t)blockIdx.x * blockDim.x + threadIdx.x;
    if (i < (size_t)NN * 128) ((float4*)g_hA)[i] = make_float4(0.f, 0.f, 0.f, 0.f);
}

// ---------------- tf32 mma helpers ----------------

__device__ __forceinline__ unsigned f2tf(float x) {
    unsigned r;
    asm("cvt.rna.tf32.f32 %0, %1;" : "=r"(r) : "f"(x));
    return r;
}

__device__ __forceinline__ void mma_tf32(float& c0, float& c1, float& c2, float& c3,
                                         unsigned a0, unsigned a1, unsigned a2, unsigned a3,
                                         unsigned b0, unsigned b1) {
    asm volatile(
        "mma.sync.aligned.m16n8k8.row.col.f32.tf32.tf32.f32 "
        "{%0,%1,%2,%3}, {%4,%5,%6,%7}, {%8,%9}, {%0,%1,%2,%3};\n"
        : "+f"(c0), "+f"(c1), "+f"(c2), "+f"(c3)
        : "r"(a0), "r"(a1), "r"(a2), "r"(a3), "r"(b0), "r"(b1));
}

// A-fragment load from UNPERMUTED activations (scalar, conflict-free banks)
__device__ __forceinline__ void load_a(unsigned a[8][4], const float* __restrict__ X,
                                       int xp, int lane) {
    int row = lane >> 2, kc = lane & 3;
    const float* p0 = X + row * xp + kc;
    const float* p1 = X + (row + 8) * xp + kc;
    #pragma unroll
    for (int kb = 0; kb < 8; kb++) {
        a[kb][0] = f2tf(p0[kb * 8]);
        a[kb][1] = f2tf(p1[kb * 8]);
        a[kb][2] = f2tf(p0[kb * 8 + 4]);
        a[kb][3] = f2tf(p1[kb * 8 + 4]);
    }
}

// EPI: 0 plain, 1 relu, 2 add residual R ; ROWS8: only rows 0..7 stored
// W is in k-permuted layout with pitch WPITCH; everything else unpermuted.
template<int EPI, bool ROWS8>
__device__ __forceinline__ void gemm_tile(const unsigned a[8][4],
                                          const float* __restrict__ W,
                                          const float* __restrict__ bias,
                                          int jbase,
                                          float* __restrict__ C, int cp,
                                          const float* __restrict__ R, int rp,
                                          int lane) {
    int g = lane >> 2, tg = lane & 3;
    int col0 = jbase + 2 * tg;
    float2 bb = *(const float2*)(bias + col0);
    float c0 = bb.x, c1 = bb.y, c2 = bb.x, c3 = bb.y;
    const float* wr = W + (jbase + g) * WPITCH;
    #pragma unroll
    for (int kb = 0; kb < 8; kb++) {
        float2 w2 = *(const float2*)(wr + kb * 8 + 2 * tg);   // (col tg, col tg+4)
        mma_tf32(c0, c1, c2, c3, a[kb][0], a[kb][1], a[kb][2], a[kb][3],
                 __float_as_uint(w2.x), __float_as_uint(w2.y));
    }
    if (EPI == 2) {
        float2 r0 = *(const float2*)(R + g * rp + col0);
        float2 r1 = *(const float2*)(R + (g + 8) * rp + col0);
        c0 += r0.x; c1 += r0.y; c2 += r1.x; c3 += r1.y;
    }
    if (EPI == 1) {
        c0 = fmaxf(c0, 0.f); c1 = fmaxf(c1, 0.f);
        c2 = fmaxf(c2, 0.f); c3 = fmaxf(c3, 0.f);
    }
    *(float2*)(C + g * cp + col0) = make_float2(c0, c1);
    if (!ROWS8) *(float2*)(C + (g + 8) * cp + col0) = make_float2(c2, c3);
}

// ---------------- main per-edge transformer kernel ----------------

#define SUBBAR() asm volatile("bar.sync %0, 128;" :: "r"(sub + 1) : "memory")

__global__ void __launch_bounds__(512, 1)
edge_kernel(const int* __restrict__ ei, int dir,
            const float* __restrict__ bpw, const float* __restrict__ bpb,
            const float* __restrict__ ipw, const float* __restrict__ ipb,
            const float* __restrict__ opw, const float* __restrict__ opb,
            const float* __restrict__ ln1g, const float* __restrict__ ln1b,
            const float* __restrict__ ln2g, const float* __restrict__ ln2b,
            const float* __restrict__ w1,  const float* __restrict__ fb1,
            const float* __restrict__ w2,  const float* __restrict__ fb2) {
    extern __shared__ float sm[];
    float* s_ipw = sm;                          // 192*72
    float* s_opw = s_ipw + 192 * WPITCH;
    float* s_w1  = s_opw + 64 * WPITCH;
    float* s_w2  = s_w1  + 64 * WPITCH;
    float* s_bw  = s_w2  + 64 * WPITCH;
    float* s_b   = s_bw  + 64 * WPITCH;         // 704 floats biases/ln
    float* s_act = s_b + 704;

    const float* hin  = dir ? g_hB : g_hA;
    float*       hout = dir ? g_hA : g_hB;

    const int tid = threadIdx.x;

    // ---- stage weights once: tf32-rounded, k-dim permuted, pitch 72 ----
    for (int i = tid; i < 192 * 64; i += 512) {
        int j = i >> 6, k = i & 63;
        int kp = (k & 56) | ((k & 3) << 1) | ((k >> 2) & 1);
        s_ipw[j * WPITCH + kp] = __uint_as_float(f2tf(ipw[i]));
    }
    for (int i = tid; i < 64 * 64; i += 512) {
        int j = i >> 6, k = i & 63;
        int kp = (k & 56) | ((k & 3) << 1) | ((k >> 2) & 1);
        int r = j * WPITCH + kp;
        s_opw[r] = __uint_as_float(f2tf(opw[i]));
        s_w1[r]  = __uint_as_float(f2tf(w1[i]));
        s_w2[r]  = __uint_as_float(f2tf(w2[i]));
        s_bw[r]  = __uint_as_float(f2tf(bpw[i]));
    }
    for (int i = tid; i < 192; i += 512) s_b[i] = ipb[i];
    if (tid < 64) {
        s_b[192 + tid] = opb[tid];  s_b[256 + tid] = fb1[tid];
        s_b[320 + tid] = fb2[tid];  s_b[384 + tid] = ln1g[tid];
        s_b[448 + tid] = ln1b[tid]; s_b[512 + tid] = ln2g[tid];
        s_b[576 + tid] = ln2b[tid]; s_b[640 + tid] = bpb[tid];
    }
    __syncthreads();

    const int sub  = tid >> 7;     // 0..3 edge slot
    const int st   = tid & 127;
    const int warp = st >> 5;
    const int lane = st & 31;
    const int g    = lane >> 2, tg = lane & 3;
    float* xs  = s_act + sub * 5888;       // 8*68
    float* xc  = xs + 8 * PITCH;           // 16*68
    float* qv  = xc + 16 * PITCH;          // 16*196 (q 0..63 | k 64..127 | vT 128..191)
    float* ao  = qv + 16 * QPITCH;         // 16*68  (P scratch / attn out / ff hidden)

    const int is64 = (g_any == 0);
    const int r0 = st >> 4, d0 = (st & 15) << 2;
    const int stride4 = gridDim.x * 4;

    // ---- prologue prefetch ----
    bool pv; int ptgt = 0; float pic = 0.f;
    float4 pvi = make_float4(0, 0, 0, 0), pvj = pvi;
    {
        int e = blockIdx.x * 4 + sub;
        pv = e < EE;
        if (pv) {
            int src = is64 ? ei[2 * e]        : ei[e];
            ptgt    = is64 ? ei[2 * (EE + e)] : ei[EE + e];
            pic = g_inv[ptgt];
            pvi = *(const float4*)(hin + (size_t)ptgt * 512 + r0 * 64 + d0);
            pvj = *(const float4*)(hin + (size_t)src  * 512 + r0 * 64 + d0);
        }
    }

    for (int base = blockIdx.x * 4; base < EE; base += stride4) {
        const bool valid = pv;
        const int  tgt = ptgt;
        const float ic = pic;

        // ---- P0: commit prefetched gather to smem ----
        if (valid) {
            *(float4*)(xc + r0 * PITCH + d0) = pvi;
            *(float4*)(xs + r0 * PITCH + d0) = pvj;
        }
        SUBBAR();

        // ---- prefetch next iteration ----
        {
            int en = base + stride4 + sub;
            pv = en < EE;
            if (pv) {
                int src = is64 ? ei[2 * en]        : ei[en];
                ptgt    = is64 ? ei[2 * (EE + en)] : ei[EE + en];
                pic = g_inv[ptgt];
                pvi = *(const float4*)(hin + (size_t)ptgt * 512 + r0 * 64 + d0);
                pvj = *(const float4*)(hin + (size_t)src  * 512 + r0 * 64 + d0);
            }
        }

        // ---- P1: bproj -> xc rows 8..15 ----
        if (valid) {
            unsigned a[8][4];
            load_a(a, xs, PITCH, lane);
            gemm_tile<0, true>(a, s_bw, s_b + 640, warp * 16,     xc + 8 * PITCH, PITCH, 0, 0, lane);
            gemm_tile<0, true>(a, s_bw, s_b + 640, warp * 16 + 8, xc + 8 * PITCH, PITCH, 0, 0, lane);
        }
        SUBBAR();

        // ---- P2: qkv ; V stored transposed per head into vT region ----
        if (valid) {
            unsigned a[8][4];
            load_a(a, xc, PITCH, lane);
            #pragma unroll
            for (int nt = 0; nt < 6; nt++) {
                int jb = warp * 48 + nt * 8;
                float2 bb = *(const float2*)(s_b + jb + 2 * tg);
                float c0 = bb.x, c1 = bb.y, c2 = bb.x, c3 = bb.y;
                const float* wr = s_ipw + (jb + g) * WPITCH;
                #pragma unroll
                for (int kb = 0; kb < 8; kb++) {
                    float2 w2 = *(const float2*)(wr + kb * 8 + 2 * tg);
                    mma_tf32(c0, c1, c2, c3, a[kb][0], a[kb][1], a[kb][2], a[kb][3],
                             __float_as_uint(w2.x), __float_as_uint(w2.y));
                }
                if (jb < 128) {
                    *(float2*)(qv + g * QPITCH + jb + 2 * tg)       = make_float2(c0, c1);
                    *(float2*)(qv + (g + 8) * QPITCH + jb + 2 * tg) = make_float2(c2, c3);
                } else {
                    // transposed V store: vT[d][key] at qv[d&15][128 + 16*(d>>4) + key]
                    int dL = jb - 128 + 2 * tg;
                    float* vt = qv + 128 + 16 * (dL >> 4);
                    int dd = dL & 15;
                    vt[dd * QPITCH + g]           = c0;
                    vt[(dd + 1) * QPITCH + g]     = c1;
                    vt[dd * QPITCH + g + 8]       = c2;
                    vt[(dd + 1) * QPITCH + g + 8] = c3;
                }
            }
        }
        SUBBAR();

        // ---- P3: attention via MMA (warp = head) ----
        if (valid) {
            const float* qb  = qv + warp * 16;
            const float* kbp = qv + 64 + warp * 16;
            unsigned aq[2][4];
            #pragma unroll
            for (int kc = 0; kc < 2; kc++) {
                const float* p0 = qb + g * QPITCH + kc * 8 + tg;
                const float* p1 = qb + (g + 8) * QPITCH + kc * 8 + tg;
                aq[kc][0] = f2tf(p0[0]); aq[kc][1] = f2tf(p1[0]);
                aq[kc][2] = f2tf(p0[4]); aq[kc][3] = f2tf(p1[4]);
            }
            float s00, s01, s02, s03, s10, s11, s12, s13;
            {
                float c0 = 0, c1 = 0, c2 = 0, c3 = 0;
                #pragma unroll
                for (int kc = 0; kc < 2; kc++) {
                    const float* kr = kbp + g * QPITCH + kc * 8;
                    mma_tf32(c0, c1, c2, c3, aq[kc][0], aq[kc][1], aq[kc][2], aq[kc][3],
                             f2tf(kr[tg]), f2tf(kr[tg + 4]));
                }
                s00 = c0; s01 = c1; s02 = c2; s03 = c3;
            }
            {
                float c0 = 0, c1 = 0, c2 = 0, c3 = 0;
                #pragma unroll
                for (int kc = 0; kc < 2; kc++) {
                    const float* kr = kbp + (8 + g) * QPITCH + kc * 8;
                    mma_tf32(c0, c1, c2, c3, aq[kc][0], aq[kc][1], aq[kc][2], aq[kc][3],
                             f2tf(kr[tg]), f2tf(kr[tg + 4]));
                }
                s10 = c0; s11 = c1; s12 = c2; s13 = c3;
            }
            s00 *= 0.25f; s01 *= 0.25f; s02 *= 0.25f; s03 *= 0.25f;
            s10 *= 0.25f; s11 *= 0.25f; s12 *= 0.25f; s13 *= 0.25f;
            float m0 = fmaxf(fmaxf(s00, s01), fmaxf(s10, s11));
            float m1 = fmaxf(fmaxf(s02, s03), fmaxf(s12, s13));
            m0 = fmaxf(m0, __shfl_xor_sync(0xffffffffu, m0, 1));
            m0 = fmaxf(m0, __shfl_xor_sync(0xffffffffu, m0, 2));
            m1 = fmaxf(m1, __shfl_xor_sync(0xffffffffu, m1, 1));
            m1 = fmaxf(m1, __shfl_xor_sync(0xffffffffu, m1, 2));
            float e00 = __expf(s00 - m0), e01 = __expf(s01 - m0);
            float e10 = __expf(s10 - m0), e11 = __expf(s11 - m0);
            float e02 = __expf(s02 - m1), e03 = __expf(s03 - m1);
            float e12 = __expf(s12 - m1), e13 = __expf(s13 - m1);
            float t0 = (e00 + e01) + (e10 + e11);
            float t1 = (e02 + e03) + (e12 + e13);
            t0 += __shfl_xor_sync(0xffffffffu, t0, 1);
            t0 += __shfl_xor_sync(0xffffffffu, t0, 2);
            t1 += __shfl_xor_sync(0xffffffffu, t1, 1);
            t1 += __shfl_xor_sync(0xffffffffu, t1, 2);
            float r0s = 1.f / t0, r1s = 1.f / t1;
            float* pb = ao + warp * 16;
            *(float2*)(pb + g * PITCH + 2 * tg)           = make_float2(e00 * r0s, e01 * r0s);
            *(float2*)(pb + g * PITCH + 8 + 2 * tg)       = make_float2(e10 * r0s, e11 * r0s);
            *(float2*)(pb + (g + 8) * PITCH + 2 * tg)     = make_float2(e02 * r1s, e03 * r1s);
            *(float2*)(pb + (g + 8) * PITCH + 8 + 2 * tg) = make_float2(e12 * r1s, e13 * r1s);
            __syncwarp();
            unsigned ap[2][4];
            #pragma unroll
            for (int kc = 0; kc < 2; kc++) {
                const float* p0 = pb + g * PITCH + kc * 8 + tg;
                const float* p1 = pb + (g + 8) * PITCH + kc * 8 + tg;
                ap[kc][0] = f2tf(p0[0]); ap[kc][1] = f2tf(p1[0]);
                ap[kc][2] = f2tf(p0[4]); ap[kc][3] = f2tf(p1[4]);
            }
            __syncwarp();
            const float* vtb = qv + 128 + 16 * warp;
            #pragma unroll
            for (int jb2 = 0; jb2 < 2; jb2++) {
                float c0 = 0, c1 = 0, c2 = 0, c3 = 0;
                #pragma unroll
                for (int kc = 0; kc < 2; kc++) {
                    const float* vr = vtb + (jb2 * 8 + g) * QPITCH + kc * 8;
                    mma_tf32(c0, c1, c2, c3, ap[kc][0], ap[kc][1], ap[kc][2], ap[kc][3],
                             f2tf(vr[tg]), f2tf(vr[tg + 4]));
                }
                *(float2*)(ao + g * PITCH + warp * 16 + jb2 * 8 + 2 * tg)       = make_float2(c0, c1);
                *(float2*)(ao + (g + 8) * PITCH + warp * 16 + jb2 * 8 + 2 * tg) = make_float2(c2, c3);
            }
        }
        SUBBAR();

        // ---- P4: out_proj + residual -> qv ----
        if (valid) {
            unsigned a[8][4];
            load_a(a, ao, PITCH, lane);
            gemm_tile<2, false>(a, s_opw, s_b + 192, warp * 16,     qv, QPITCH, xc, PITCH, lane);
            gemm_tile<2, false>(a, s_opw, s_b + 192, warp * 16 + 8, qv, QPITCH, xc, PITCH, lane);
        }
        SUBBAR();

        // ---- LN1 (8 threads/row) -> xc ----
        if (valid) {
            int row = st >> 3, part = st & 7, c0i = part * 8;
            const float4* p = (const float4*)(qv + row * QPITCH + c0i);
            float4 u0 = p[0], u1 = p[1];
            float s = (u0.x + u0.y) + (u0.z + u0.w) + (u1.x + u1.y) + (u1.z + u1.w);
            s += __shfl_xor_sync(0xffffffffu, s, 1);
            s += __shfl_xor_sync(0xffffffffu, s, 2);
            s += __shfl_xor_sync(0xffffffffu, s, 4);
            float mu = s * 0.015625f;
            float t0 = u0.x - mu, t1 = u0.y - mu, t2 = u0.z - mu, t3 = u0.w - mu;
            float t4 = u1.x - mu, t5 = u1.y - mu, t6 = u1.z - mu, t7 = u1.w - mu;
            float v = t0*t0 + t1*t1 + t2*t2 + t3*t3 + t4*t4 + t5*t5 + t6*t6 + t7*t7;
            v += __shfl_xor_sync(0xffffffffu, v, 1);
            v += __shfl_xor_sync(0xffffffffu, v, 2);
            v += __shfl_xor_sync(0xffffffffu, v, 4);
            float rstd = rsqrtf(v * 0.015625f + 1e-5f);
            const float4 g0 = *(const float4*)(s_b + 384 + c0i);
            const float4 g1 = *(const float4*)(s_b + 384 + c0i + 4);
            const float4 bb0 = *(const float4*)(s_b + 448 + c0i);
            const float4 bb1 = *(const float4*)(s_b + 448 + c0i + 4);
            float4 o0, o1;
            o0.x = t0 * rstd * g0.x + bb0.x; o0.y = t1 * rstd * g0.y + bb0.y;
            o0.z = t2 * rstd * g0.z + bb0.z; o0.w = t3 * rstd * g0.w + bb0.w;
            o1.x = t4 * rstd * g1.x + bb1.x; o1.y = t5 * rstd * g1.y + bb1.y;
            o1.z = t6 * rstd * g1.z + bb1.z; o1.w = t7 * rstd * g1.w + bb1.w;
            *(float4*)(xc + row * PITCH + c0i) = o0;
            *(float4*)(xc + row * PITCH + c0i + 4) = o1;
        }
        SUBBAR();

        // ---- P6: FF1 + relu -> ao ----
        if (valid) {
            unsigned a[8][4];
            load_a(a, xc, PITCH, lane);
            gemm_tile<1, false>(a, s_w1, s_b + 256, warp * 16,     ao, PITCH, 0, 0, lane);
            gemm_tile<1, false>(a, s_w1, s_b + 256, warp * 16 + 8, ao, PITCH, 0, 0, lane);
        }
        SUBBAR();

        // ---- P7: FF2 + residual -> qv ----
        if (valid) {
            unsigned a[8][4];
            load_a(a, ao, PITCH, lane);
            gemm_tile<2, false>(a, s_w2, s_b + 320, warp * 16,     qv, QPITCH, xc, PITCH, lane);
            gemm_tile<2, false>(a, s_w2, s_b + 320, warp * 16 + 8, qv, QPITCH, xc, PITCH, lane);
        }
        SUBBAR();

        // ---- LN2 (rows 0..7) + scaled vector-atomic scatter ----
        if (valid) {
            int row = st >> 4, part = st & 15, c0i = part * 4;
            float4 u = *(const float4*)(qv + row * QPITCH + c0i);
            float s = (u.x + u.y) + (u.z + u.w);
            s += __shfl_xor_sync(0xffffffffu, s, 1);
            s += __shfl_xor_sync(0xffffffffu, s, 2);
            s += __shfl_xor_sync(0xffffffffu, s, 4);
            s += __shfl_xor_sync(0xffffffffu, s, 8);
            float mu = s * 0.015625f;
            float t0 = u.x - mu, t1 = u.y - mu, t2 = u.z - mu, t3 = u.w - mu;
            float v = t0*t0 + t1*t1 + t2*t2 + t3*t3;
            v += __shfl_xor_sync(0xffffffffu, v, 1);
            v += __shfl_xor_sync(0xffffffffu, v, 2);
            v += __shfl_xor_sync(0xffffffffu, v, 4);
            v += __shfl_xor_sync(0xffffffffu, v, 8);
            float rstd = rsqrtf(v * 0.015625f + 1e-5f);
            const float4 gg = *(const float4*)(s_b + 512 + c0i);
            const float4 bb = *(const float4*)(s_b + 576 + c0i);
            float o0 = (t0 * rstd * gg.x + bb.x) * ic;
            float o1 = (t1 * rstd * gg.y + bb.y) * ic;
            float o2 = (t2 * rstd * gg.z + bb.z) * ic;
            float o3 = (t3 * rstd * gg.w + bb.w) * ic;
            float* dst = hout + (size_t)tgt * 512 + row * 64 + c0i;
            asm volatile("red.global.add.v4.f32 [%0], {%1,%2,%3,%4};"
                         :: "l"(dst), "f"(o0), "f"(o1), "f"(o2), "f"(o3) : "memory");
        }
        // no trailing barrier: next write to qv is P2 (two barriers away)
    }
}

// ---------------- output head ----------------
__global__ void out_kernel(const float* __restrict__ ow,
                           const float* __restrict__ ob,
                           float* __restrict__ out) {
    __shared__ float shs[8][64];
    int w = threadIdx.x >> 5, lane = threadIdx.x & 31;
    int n = blockIdx.x * 8 + w;
    if (n >= NN) return;
    const float* hr = g_hA + (size_t)n * 512;
    float lo = 0.f, hi = 0.f;
    #pragma unroll
    for (int c = 0; c < 8; c++) { lo += hr[c * 64 + lane]; hi += hr[c * 64 + 32 + lane]; }
    shs[w][lane] = lo; shs[w][lane + 32] = hi;
    __syncwarp();
    float z = -1e30f;
    if (lane < 16) {
        float acc = 8.f * ob[lane];
        const float* wr = ow + lane * 64;
        #pragma unroll
        for (int d = 0; d < 64; d++) acc = fmaf(shs[w][d], wr[d], acc);
        z = acc;
    }
    float m = z;
    #pragma unroll
    for (int off = 8; off; off >>= 1) m = fmaxf(m, __shfl_xor_sync(0xffffffffu, m, off, 16));
    float p = __expf(z - m);
    float s = p;
    #pragma unroll
    for (int off = 8; off; off >>= 1) s += __shfl_xor_sync(0xffffffffu, s, off, 16);
    if (lane < 16) out[n * 16 + lane] = p / s;
}

// ---------------- launch ----------------
extern "C" void kernel_launch(void* const* d_in, const int* in_sizes, int n_in,
                              void* d_out, int out_size) {
    const float* x    = (const float*)d_in[0];
    const int*   ei   = (const int*)d_in[1];
    const float* numw = (const float*)d_in[2];
    const float* numb = (const float*)d_in[3];
    const float* bpw  = (const float*)d_in[4];
    const float* bpb  = (const float*)d_in[5];
    const float* ipw  = (const float*)d_in[6];
    const float* ipb  = (const float*)d_in[7];
    const float* opw  = (const float*)d_in[8];
    const float* opb  = (const float*)d_in[9];
    const float* g1   = (const float*)d_in[10];
    const float* b1   = (const float*)d_in[11];
    const float* g2   = (const float*)d_in[12];
    const float* b2   = (const float*)d_in[13];
    const float* w1   = (const float*)d_in[14];
    const float* fb1  = (const float*)d_in[15];
    const float* w2   = (const float*)d_in[16];
    const float* fb2  = (const float*)d_in[17];
    const float* ow   = (const float*)d_in[18];
    const float* ob   = (const float*)d_in[19];
    float* out = (float*)d_out;

    const int SMEM_BYTES = (192 * WPITCH + 4 * 64 * WPITCH + 704 + 4 * 5888) * 4;
    cudaFuncSetAttribute(edge_kernel, cudaFuncAttributeMaxDynamicSharedMemorySize, SMEM_BYTES);

    int dev = 0, sms = 148;
    cudaGetDevice(&dev);
    cudaDeviceGetAttribute(&sms, cudaDevAttrMultiProcessorCount, dev);

    setup0_kernel<<<(NN * 128 + 255) / 256, 256>>>();
    detect_kernel<<<256, 256>>>(ei);
    embed_kernel<<<(NN * 512 + 255) / 256, 256>>>(x, numw, numb);
    count_kernel<<<(EE + 255) / 256, 256>>>(ei);
    fin_cnt_kernel<<<(NN + 255) / 256, 256>>>();

    // layer 0: A -> B
    edge_kernel<<<sms, 512, SMEM_BYTES>>>(ei, 0,
        bpw, bpb, ipw, ipb, opw, opb, g1, b1, g2, b2, w1, fb1, w2, fb2);

    // layer 1: B -> A
    zeroA_kernel<<<(NN * 128 + 255) / 256, 256>>>();
    edge_kernel<<<sms, 512, SMEM_BYTES>>>(ei, 1,
        bpw + 64 * 64, bpb + 64, ipw + 192 * 64, ipb + 192, opw + 64 * 64, opb + 64,
        g1 + 64, b1 + 64, g2 + 64, b2 + 64,
        w1 + 64 * 64, fb1 + 64, w2 + 64 * 64, fb2 + 64);

    out_kernel<<<(NN + 7) / 8, 256>>>(ow, ob, out);
}

// round 8
// speedup vs baseline: 2.0181x; 1.4034x over previous
#include <cuda_runtime.h>
#include <cuda_fp16.h>

#define NN 50000
#define EE 100000

// word offsets in dynamic smem
#define OFF_WQ  704
#define OFF_WO  (OFF_WQ + 192*36)
#define OFF_W1  (OFF_WO + 64*36)
#define OFF_W2  (OFF_W1 + 64*36)
#define OFF_WB  (OFF_W2 + 64*36)
#define OFF_ACT (OFF_WB + 64*36)
// per-sub layout (words): xsh 0(288) xch 288(576) aoh 864(576) qvh 1440(1088)
//                         vpw 2528(768) xcf 3296(1088 f32) qvf 4384(1088 f32)
#define SUBW 5472
#define SMEM_WORDS (OFF_ACT + 4*SUBW)

__device__ float g_hA[(size_t)NN * 512];
__device__ float g_hB[(size_t)NN * 512];
__device__ float g_inv[NN];
__device__ int   g_any;

__global__ void setup0_kernel() {
    size_t i = (size_t)blockIdx.x * blockDim.x + threadIdx.x;
    if (i == 0) g_any = 0;
    if (i < NN) g_inv[i] = 0.f;
    if (i < (size_t)NN * 128) ((float4*)g_hB)[i] = make_float4(0.f, 0.f, 0.f, 0.f);
}
__global__ void detect_kernel(const int* __restrict__ ei) {
    int i = blockIdx.x * blockDim.x + threadIdx.x;
    int v = 0;
    for (int k = i; k < EE; k += gridDim.x * blockDim.x) v |= ei[2 * k + 1];
    if (v) atomicOr(&g_any, 1);
}
__global__ void embed_kernel(const float* __restrict__ x, const float* __restrict__ nw,
                             const float* __restrict__ nb) {
    int i = blockIdx.x * blockDim.x + threadIdx.x;
    if (i < NN * 512) {
        int n = i >> 9, r = i & 511;
        g_hA[i] = x[n * 8 + (r >> 6)] * nw[r] + nb[r];
    }
}
__global__ void count_kernel(const int* __restrict__ ei) {
    int e = blockIdx.x * blockDim.x + threadIdx.x;
    if (e < EE) {
        int t = (g_any == 0) ? ei[2 * (EE + e)] : ei[EE + e];
        atomicAdd(&g_inv[t], 1.0f);
    }
}
__global__ void fin_cnt_kernel() {
    int i = blockIdx.x * blockDim.x + threadIdx.x;
    if (i < NN) g_inv[i] = 1.0f / fmaxf(g_inv[i], 1.0f);
}
__global__ void zeroA_kernel() {
    size_t i = (size_t)blockIdx.x * blockDim.x + threadIdx.x;
    if (i < (size_t)NN * 128) ((float4*)g_hA)[i] = make_float4(0.f, 0.f, 0.f, 0.f);
}

// ---- f16 mma helpers ----
__device__ __forceinline__ void mma_f16(float& c0, float& c1, float& c2, float& c3,
                                        unsigned a0, unsigned a1, unsigned a2, unsigned a3,
                                        unsigned b0, unsigned b1) {
    asm volatile(
        "mma.sync.aligned.m16n8k16.row.col.f32.f16.f16.f32 "
        "{%0,%1,%2,%3}, {%4,%5,%6,%7}, {%8,%9}, {%0,%1,%2,%3};\n"
        : "+f"(c0), "+f"(c1), "+f"(c2), "+f"(c3)
        : "r"(a0), "r"(a1), "r"(a2), "r"(a3), "r"(b0), "r"(b1));
}
__device__ __forceinline__ unsigned packh2(float hi, float lo) {
    unsigned d;
    asm("cvt.rn.f16x2.f32 %0, %1, %2;" : "=r"(d) : "f"(hi), "f"(lo));
    return d;
}
// A fragments (4 k16-chunks) from half buffer with row pitch rpw words
__device__ __forceinline__ void load_ah(unsigned a[4][4], const unsigned* __restrict__ X,
                                        int rpw, int lane) {
    int row = lane >> 2, tg = lane & 3;
    const unsigned* p0 = X + row * rpw + tg;
    const unsigned* p1 = X + (row + 8) * rpw + tg;
    #pragma unroll
    for (int kc = 0; kc < 4; kc++) {
        a[kc][0] = p0[kc * 8];
        a[kc][1] = p1[kc * 8];
        a[kc][2] = p0[kc * 8 + 4];
        a[kc][3] = p1[kc * 8 + 4];
    }
}
// EPI: 0 plain, 1 relu, 2 +residual R(f32). HOUT: half2 out Ch; FOUT: f32 out Cf.
template<int EPI, bool ROWS8, bool HOUT, bool FOUT>
__device__ __forceinline__ void gemm_tile_h(const unsigned a[4][4],
                                            const unsigned* __restrict__ W,
                                            const float* __restrict__ bias, int jbase,
                                            unsigned* __restrict__ Ch, int chw,
                                            float* __restrict__ Cf, int cfw,
                                            const float* __restrict__ R, int rw, int lane) {
    int g = lane >> 2, tg = lane & 3;
    int col0 = jbase + 2 * tg;
    float2 bb = *(const float2*)(bias + col0);
    float c0 = bb.x, c1 = bb.y, c2 = bb.x, c3 = bb.y;
    const unsigned* wr = W + (jbase + g) * 36 + tg;
    #pragma unroll
    for (int kc = 0; kc < 4; kc++)
        mma_f16(c0, c1, c2, c3, a[kc][0], a[kc][1], a[kc][2], a[kc][3],
                wr[kc * 8], wr[kc * 8 + 4]);
    if (EPI == 2) {
        float2 r0 = *(const float2*)(R + g * rw + col0);
        float2 r1 = *(const float2*)(R + (g + 8) * rw + col0);
        c0 += r0.x; c1 += r0.y; c2 += r1.x; c3 += r1.y;
    }
    if (EPI == 1) {
        c0 = fmaxf(c0, 0.f); c1 = fmaxf(c1, 0.f);
        c2 = fmaxf(c2, 0.f); c3 = fmaxf(c3, 0.f);
    }
    if (HOUT) {
        Ch[g * chw + (jbase >> 1) + tg] = packh2(c1, c0);
        if (!ROWS8) Ch[(g + 8) * chw + (jbase >> 1) + tg] = packh2(c3, c2);
    }
    if (FOUT) {
        *(float2*)(Cf + g * cfw + col0) = make_float2(c0, c1);
        if (!ROWS8) *(float2*)(Cf + (g + 8) * cfw + col0) = make_float2(c2, c3);
    }
}

#define SUBBAR() asm volatile("bar.sync %0, 128;" :: "r"(sub + 1) : "memory")

__global__ void __launch_bounds__(512, 1)
edge_kernel(const int* __restrict__ ei, int dir,
            const float* __restrict__ bpw, const float* __restrict__ bpb,
            const float* __restrict__ ipw, const float* __restrict__ ipb,
            const float* __restrict__ opw, const float* __restrict__ opb,
            const float* __restrict__ ln1g, const float* __restrict__ ln1b,
            const float* __restrict__ ln2g, const float* __restrict__ ln2b,
            const float* __restrict__ w1,  const float* __restrict__ fb1,
            const float* __restrict__ w2,  const float* __restrict__ fb2) {
    extern __shared__ float sm[];
    unsigned* smw = (unsigned*)sm;
    float* s_b = sm;
    __half* whq = (__half*)(smw + OFF_WQ);
    __half* who = (__half*)(smw + OFF_WO);
    __half* wh1 = (__half*)(smw + OFF_W1);
    __half* wh2 = (__half*)(smw + OFF_W2);
    __half* whb = (__half*)(smw + OFF_WB);

    const float* hin  = dir ? g_hB : g_hA;
    float*       hout = dir ? g_hA : g_hB;
    const int tid = threadIdx.x;

    // stage weights as fp16 (pitch 72 halfs = 36 words), biases/ln as f32
    for (int i = tid; i < 192 * 64; i += 512)
        whq[(i >> 6) * 72 + (i & 63)] = __float2half_rn(ipw[i]);
    for (int i = tid; i < 64 * 64; i += 512) {
        int r = (i >> 6) * 72 + (i & 63);
        who[r] = __float2half_rn(opw[i]);
        wh1[r] = __float2half_rn(w1[i]);
        wh2[r] = __float2half_rn(w2[i]);
        whb[r] = __float2half_rn(bpw[i]);
    }
    for (int i = tid; i < 192; i += 512) s_b[i] = ipb[i];
    if (tid < 64) {
        s_b[192 + tid] = opb[tid];  s_b[256 + tid] = fb1[tid];
        s_b[320 + tid] = fb2[tid];  s_b[384 + tid] = ln1g[tid];
        s_b[448 + tid] = ln1b[tid]; s_b[512 + tid] = ln2g[tid];
        s_b[576 + tid] = ln2b[tid]; s_b[640 + tid] = bpb[tid];
    }
    __syncthreads();

    const int sub  = tid >> 7;
    const int st   = tid & 127;
    const int warp = st >> 5;
    const int lane = st & 31;
    const int g    = lane >> 2, tg = lane & 3;

    unsigned* subw = smw + OFF_ACT + sub * SUBW;
    unsigned* xsh = subw;                    // 8 x 36 half2 words
    unsigned* xch = subw + 288;              // 16 x 36
    unsigned* aoh = subw + 864;              // 16 x 36
    unsigned* qvh = subw + 1440;             // 16 x 68 (q words 0..31 | k 32..63)
    unsigned* vpw = subw + 2528;             // 64 x 12 (V^T: row=d, halfs=keys)
    __half*   vph = (__half*)vpw;
    float*    xcf = sm + OFF_ACT + sub * SUBW + 3296;  // 16 x 68 f32
    float*    qvf = sm + OFF_ACT + sub * SUBW + 4384;  // 16 x 68 f32

    const unsigned* Wq = smw + OFF_WQ;
    const unsigned* Wo = smw + OFF_WO;
    const unsigned* W1p = smw + OFF_W1;
    const unsigned* W2p = smw + OFF_W2;
    const unsigned* Wb = smw + OFF_WB;

    const int is64 = (g_any == 0);
    const int r0 = st >> 4, d0 = (st & 15) << 2;
    const int stride4 = gridDim.x * 4;

    bool pv; int ptgt = 0; float pic = 0.f;
    float4 pvi = make_float4(0, 0, 0, 0), pvj = pvi;
    {
        int e = blockIdx.x * 4 + sub;
        pv = e < EE;
        if (pv) {
            int src = is64 ? ei[2 * e]        : ei[e];
            ptgt    = is64 ? ei[2 * (EE + e)] : ei[EE + e];
            pic = g_inv[ptgt];
            pvi = *(const float4*)(hin + (size_t)ptgt * 512 + r0 * 64 + d0);
            pvj = *(const float4*)(hin + (size_t)src  * 512 + r0 * 64 + d0);
        }
    }

    for (int base = blockIdx.x * 4; base < EE; base += stride4) {
        const bool valid = pv;
        const int  tgt = ptgt;
        const float ic = pic;

        // P0: commit gather: f32 residual + half copies
        if (valid) {
            *(float4*)(xcf + r0 * 68 + d0) = pvi;
            int wb = r0 * 36 + (d0 >> 1);
            xch[wb]     = packh2(pvi.y, pvi.x);
            xch[wb + 1] = packh2(pvi.w, pvi.z);
            xsh[wb]     = packh2(pvj.y, pvj.x);
            xsh[wb + 1] = packh2(pvj.w, pvj.z);
        }
        SUBBAR();

        // prefetch next
        {
            int en = base + stride4 + sub;
            pv = en < EE;
            if (pv) {
                int src = is64 ? ei[2 * en]        : ei[en];
                ptgt    = is64 ? ei[2 * (EE + en)] : ei[EE + en];
                pic = g_inv[ptgt];
                pvi = *(const float4*)(hin + (size_t)ptgt * 512 + r0 * 64 + d0);
                pvj = *(const float4*)(hin + (size_t)src  * 512 + r0 * 64 + d0);
            }
        }

        // P1: bproj -> rows 8..15 of xch (half) + xcf (f32)
        if (valid) {
            unsigned a[4][4];
            load_ah(a, xsh, 36, lane);   // rows 8..15 read garbage (discarded)
            gemm_tile_h<0, true, true, true>(a, Wb, s_b + 640, warp * 16,
                                             xch + 8 * 36, 36, xcf + 8 * 68, 68, 0, 0, lane);
            gemm_tile_h<0, true, true, true>(a, Wb, s_b + 640, warp * 16 + 8,
                                             xch + 8 * 36, 36, xcf + 8 * 68, 68, 0, 0, lane);
        }
        SUBBAR();

        // P2: qkv. q/k -> qvh packed; V -> vph transposed (row=d, halfs=keys)
        if (valid) {
            unsigned a[4][4];
            load_ah(a, xch, 36, lane);
            #pragma unroll
            for (int nt = 0; nt < 6; nt++) {
                int jb = warp * 48 + nt * 8;
                int col0 = jb + 2 * tg;
                float2 bb = *(const float2*)(s_b + col0);
                float c0 = bb.x, c1 = bb.y, c2 = bb.x, c3 = bb.y;
                const unsigned* wr = Wq + (jb + g) * 36 + tg;
                #pragma unroll
                for (int kc = 0; kc < 4; kc++)
                    mma_f16(c0, c1, c2, c3, a[kc][0], a[kc][1], a[kc][2], a[kc][3],
                            wr[kc * 8], wr[kc * 8 + 4]);
                if (jb < 128) {
                    qvh[g * 68 + (jb >> 1) + tg]       = packh2(c1, c0);
                    qvh[(g + 8) * 68 + (jb >> 1) + tg] = packh2(c3, c2);
                } else {
                    int dL = jb - 128 + 2 * tg;
                    vph[dL * 24 + g]           = __float2half_rn(c0);
                    vph[(dL + 1) * 24 + g]     = __float2half_rn(c1);
                    vph[dL * 24 + g + 8]       = __float2half_rn(c2);
                    vph[(dL + 1) * 24 + g + 8] = __float2half_rn(c3);
                }
            }
        }
        SUBBAR();

        // P3: attention (warp = head). P kept in registers.
        if (valid) {
            const unsigned* qb = qvh + warp * 8;
            const unsigned* kb = qvh + 32 + warp * 8;
            unsigned a0 = qb[g * 68 + tg],       a1 = qb[(g + 8) * 68 + tg];
            unsigned a2 = qb[g * 68 + tg + 4],   a3 = qb[(g + 8) * 68 + tg + 4];
            float s00 = 0, s01 = 0, s02 = 0, s03 = 0;
            float s10 = 0, s11 = 0, s12 = 0, s13 = 0;
            mma_f16(s00, s01, s02, s03, a0, a1, a2, a3,
                    kb[g * 68 + tg], kb[g * 68 + tg + 4]);
            mma_f16(s10, s11, s12, s13, a0, a1, a2, a3,
                    kb[(g + 8) * 68 + tg], kb[(g + 8) * 68 + tg + 4]);
            s00 *= 0.25f; s01 *= 0.25f; s02 *= 0.25f; s03 *= 0.25f;
            s10 *= 0.25f; s11 *= 0.25f; s12 *= 0.25f; s13 *= 0.25f;
            float m0 = fmaxf(fmaxf(s00, s01), fmaxf(s10, s11));
            float m1 = fmaxf(fmaxf(s02, s03), fmaxf(s12, s13));
            m0 = fmaxf(m0, __shfl_xor_sync(0xffffffffu, m0, 1));
            m0 = fmaxf(m0, __shfl_xor_sync(0xffffffffu, m0, 2));
            m1 = fmaxf(m1, __shfl_xor_sync(0xffffffffu, m1, 1));
            m1 = fmaxf(m1, __shfl_xor_sync(0xffffffffu, m1, 2));
            float e00 = __expf(s00 - m0), e01 = __expf(s01 - m0);
            float e10 = __expf(s10 - m0), e11 = __expf(s11 - m0);
            float e02 = __expf(s02 - m1), e03 = __expf(s03 - m1);
            float e12 = __expf(s12 - m1), e13 = __expf(s13 - m1);
            float t0 = (e00 + e01) + (e10 + e11);
            float t1 = (e02 + e03) + (e12 + e13);
            t0 += __shfl_xor_sync(0xffffffffu, t0, 1);
            t0 += __shfl_xor_sync(0xffffffffu, t0, 2);
            t1 += __shfl_xor_sync(0xffffffffu, t1, 1);
            t1 += __shfl_xor_sync(0xffffffffu, t1, 2);
            float r0s = 1.f / t0, r1s = 1.f / t1;
            // P as A-fragment (registers): rows g/g+8, keys = k-dim
            unsigned ap0 = packh2(e01 * r0s, e00 * r0s);
            unsigned ap1 = packh2(e03 * r1s, e02 * r1s);
            unsigned ap2 = packh2(e11 * r0s, e10 * r0s);
            unsigned ap3 = packh2(e13 * r1s, e12 * r1s);
            const unsigned* vb = vpw + warp * 16 * 12;
            #pragma unroll
            for (int jb2 = 0; jb2 < 2; jb2++) {
                float c0 = 0, c1 = 0, c2 = 0, c3 = 0;
                const unsigned* vr = vb + (jb2 * 8 + g) * 12 + tg;
                mma_f16(c0, c1, c2, c3, ap0, ap1, ap2, ap3, vr[0], vr[4]);
                aoh[g * 36 + warp * 8 + jb2 * 4 + tg]       = packh2(c1, c0);
                aoh[(g + 8) * 36 + warp * 8 + jb2 * 4 + tg] = packh2(c3, c2);
            }
        }
        SUBBAR();

        // P4: out_proj + residual(xcf) -> qvf (f32)
        if (valid) {
            unsigned a[4][4];
            load_ah(a, aoh, 36, lane);
            gemm_tile_h<2, false, false, true>(a, Wo, s_b + 192, warp * 16,
                                               0, 0, qvf, 68, xcf, 68, lane);
            gemm_tile_h<2, false, false, true>(a, Wo, s_b + 192, warp * 16 + 8,
                                               0, 0, qvf, 68, xcf, 68, lane);
        }
        SUBBAR();

        // LN1 (8 threads/row): qvf -> xcf (f32) + xch (half)
        if (valid) {
            int row = st >> 3, part = st & 7, c0i = part * 8;
            const float4* p = (const float4*)(qvf + row * 68 + c0i);
            float4 u0 = p[0], u1 = p[1];
            float s = (u0.x + u0.y) + (u0.z + u0.w) + (u1.x + u1.y) + (u1.z + u1.w);
            s += __shfl_xor_sync(0xffffffffu, s, 1);
            s += __shfl_xor_sync(0xffffffffu, s, 2);
            s += __shfl_xor_sync(0xffffffffu, s, 4);
            float mu = s * 0.015625f;
            float t0 = u0.x - mu, t1 = u0.y - mu, t2 = u0.z - mu, t3 = u0.w - mu;
            float t4 = u1.x - mu, t5 = u1.y - mu, t6 = u1.z - mu, t7 = u1.w - mu;
            float v = t0*t0 + t1*t1 + t2*t2 + t3*t3 + t4*t4 + t5*t5 + t6*t6 + t7*t7;
            v += __shfl_xor_sync(0xffffffffu, v, 1);
            v += __shfl_xor_sync(0xffffffffu, v, 2);
            v += __shfl_xor_sync(0xffffffffu, v, 4);
            float rstd = rsqrtf(v * 0.015625f + 1e-5f);
            const float4 g0 = *(const float4*)(s_b + 384 + c0i);
            const float4 g1 = *(const float4*)(s_b + 384 + c0i + 4);
            const float4 b0 = *(const float4*)(s_b + 448 + c0i);
            const float4 b1 = *(const float4*)(s_b + 448 + c0i + 4);
            float o0 = t0 * rstd * g0.x + b0.x, o1 = t1 * rstd * g0.y + b0.y;
            float o2 = t2 * rstd * g0.z + b0.z, o3 = t3 * rstd * g0.w + b0.w;
            float o4 = t4 * rstd * g1.x + b1.x, o5 = t5 * rstd * g1.y + b1.y;
            float o6 = t6 * rstd * g1.z + b1.z, o7 = t7 * rstd * g1.w + b1.w;
            *(float4*)(xcf + row * 68 + c0i)     = make_float4(o0, o1, o2, o3);
            *(float4*)(xcf + row * 68 + c0i + 4) = make_float4(o4, o5, o6, o7);
            int wb = row * 36 + part * 4;
            xch[wb]     = packh2(o1, o0);
            xch[wb + 1] = packh2(o3, o2);
            xch[wb + 2] = packh2(o5, o4);
            xch[wb + 3] = packh2(o7, o6);
        }
        SUBBAR();

        // P6: FF1 + relu -> aoh (half)
        if (valid) {
            unsigned a[4][4];
            load_ah(a, xch, 36, lane);
            gemm_tile_h<1, false, true, false>(a, W1p, s_b + 256, warp * 16,
                                               aoh, 36, 0, 0, 0, 0, lane);
            gemm_tile_h<1, false, true, false>(a, W1p, s_b + 256, warp * 16 + 8,
                                               aoh, 36, 0, 0, 0, 0, lane);
        }
        SUBBAR();

        // P7: FF2 + residual(xcf) -> qvf (f32)
        if (valid) {
            unsigned a[4][4];
            load_ah(a, aoh, 36, lane);
            gemm_tile_h<2, false, false, true>(a, W2p, s_b + 320, warp * 16,
                                               0, 0, qvf, 68, xcf, 68, lane);
            gemm_tile_h<2, false, false, true>(a, W2p, s_b + 320, warp * 16 + 8,
                                               0, 0, qvf, 68, xcf, 68, lane);
        }
        SUBBAR();

        // LN2 (rows 0..7, 16 threads/row) + vector atomic scatter
        if (valid) {
            int row = st >> 4, part = st & 15, c0i = part * 4;
            float4 u = *(const float4*)(qvf + row * 68 + c0i);
            float s = (u.x + u.y) + (u.z + u.w);
            s += __shfl_xor_sync(0xffffffffu, s, 1);
            s += __shfl_xor_sync(0xffffffffu, s, 2);
            s += __shfl_xor_sync(0xffffffffu, s, 4);
            s += __shfl_xor_sync(0xffffffffu, s, 8);
            float mu = s * 0.015625f;
            float t0 = u.x - mu, t1 = u.y - mu, t2 = u.z - mu, t3 = u.w - mu;
            float v = t0*t0 + t1*t1 + t2*t2 + t3*t3;
            v += __shfl_xor_sync(0xffffffffu, v, 1);
            v += __shfl_xor_sync(0xffffffffu, v, 2);
            v += __shfl_xor_sync(0xffffffffu, v, 4);
            v += __shfl_xor_sync(0xffffffffu, v, 8);
            float rstd = rsqrtf(v * 0.015625f + 1e-5f);
            const float4 gg = *(const float4*)(s_b + 512 + c0i);
            const float4 bb = *(const float4*)(s_b + 576 + c0i);
            float o0 = (t0 * rstd * gg.x + bb.x) * ic;
            float o1 = (t1 * rstd * gg.y + bb.y) * ic;
            float o2 = (t2 * rstd * gg.z + bb.z) * ic;
            float o3 = (t3 * rstd * gg.w + bb.w) * ic;
            float* dst = hout + (size_t)tgt * 512 + row * 64 + c0i;
            asm volatile("red.global.add.v4.f32 [%0], {%1,%2,%3,%4};"
                         :: "l"(dst), "f"(o0), "f"(o1), "f"(o2), "f"(o3) : "memory");
        }
        // no trailing barrier: P0 writes xcf rows 0..7/xch/xsh, disjoint from qvf reads
    }
}

__global__ void out_kernel(const float* __restrict__ ow, const float* __restrict__ ob,
                           float* __restrict__ out) {
    __shared__ float shs[8][64];
    int w = threadIdx.x >> 5, lane = threadIdx.x & 31;
    int n = blockIdx.x * 8 + w;
    if (n >= NN) return;
    const float* hr = g_hA + (size_t)n * 512;
    float lo = 0.f, hi = 0.f;
    #pragma unroll
    for (int c = 0; c < 8; c++) { lo += hr[c * 64 + lane]; hi += hr[c * 64 + 32 + lane]; }
    shs[w][lane] = lo; shs[w][lane + 32] = hi;
    __syncwarp();
    float z = -1e30f;
    if (lane < 16) {
        float acc = 8.f * ob[lane];
        const float* wr = ow + lane * 64;
        #pragma unroll
        for (int d = 0; d < 64; d++) acc = fmaf(shs[w][d], wr[d], acc);
        z = acc;
    }
    float m = z;
    #pragma unroll
    for (int off = 8; off; off >>= 1) m = fmaxf(m, __shfl_xor_sync(0xffffffffu, m, off, 16));
    float p = __expf(z - m);
    float s = p;
    #pragma unroll
    for (int off = 8; off; off >>= 1) s += __shfl_xor_sync(0xffffffffu, s, off, 16);
    if (lane < 16) out[n * 16 + lane] = p / s;
}

extern "C" void kernel_launch(void* const* d_in, const int* in_sizes, int n_in,
                              void* d_out, int out_size) {
    const float* x    = (const float*)d_in[0];
    const int*   ei   = (const int*)d_in[1];
    const float* numw = (const float*)d_in[2];
    const float* numb = (const float*)d_in[3];
    const float* bpw  = (const float*)d_in[4];
    const float* bpb  = (const float*)d_in[5];
    const float* ipw  = (const float*)d_in[6];
    const float* ipb  = (const float*)d_in[7];
    const float* opw  = (const float*)d_in[8];
    const float* opb  = (const float*)d_in[9];
    const float* g1   = (const float*)d_in[10];
    const float* b1   = (const float*)d_in[11];
    const float* g2   = (const float*)d_in[12];
    const float* b2   = (const float*)d_in[13];
    const float* w1   = (const float*)d_in[14];
    const float* fb1  = (const float*)d_in[15];
    const float* w2   = (const float*)d_in[16];
    const float* fb2  = (const float*)d_in[17];
    const float* ow   = (const float*)d_in[18];
    const float* ob   = (const float*)d_in[19];
    float* out = (float*)d_out;

    const int SMEM_BYTES = SMEM_WORDS * 4;
    cudaFuncSetAttribute(edge_kernel, cudaFuncAttributeMaxDynamicSharedMemorySize, SMEM_BYTES);

    int dev = 0, sms = 148;
    cudaGetDevice(&dev);
    cudaDeviceGetAttribute(&sms, cudaDevAttrMultiProcessorCount, dev);

    setup0_kernel<<<(NN * 128 + 255) / 256, 256>>>();
    detect_kernel<<<256, 256>>>(ei);
    embed_kernel<<<(NN * 512 + 255) / 256, 256>>>(x, numw, numb);
    count_kernel<<<(EE + 255) / 256, 256>>>(ei);
    fin_cnt_kernel<<<(NN + 255) / 256, 256>>>();

    edge_kernel<<<sms, 512, SMEM_BYTES>>>(ei, 0,
        bpw, bpb, ipw, ipb, opw, opb, g1, b1, g2, b2, w1, fb1, w2, fb2);

    zeroA_kernel<<<(NN * 128 + 255) / 256, 256>>>();
    edge_kernel<<<sms, 512, SMEM_BYTES>>>(ei, 1,
        bpw + 64 * 64, bpb + 64, ipw + 192 * 64, ipb + 192, opw + 64 * 64, opb + 64,
        g1 + 64, b1 + 64, g2 + 64, b2 + 64,
        w1 + 64 * 64, fb1 + 64, w2 + 64 * 64, fb2 + 64);

    out_kernel<<<(NN + 7) / 8, 256>>>(ow, ob, out);
}

// round 9
// speedup vs baseline: 2.4885x; 1.2331x over previous
#include <cuda_runtime.h>
#include <cuda_fp16.h>

#define NN 50000
#define EE 100000

// word offsets in dynamic smem
#define OFF_WQ  704
#define OFF_WO  (OFF_WQ + 192*36)
#define OFF_W1  (OFF_WO + 64*36)
#define OFF_W2  (OFF_W1 + 64*36)
#define OFF_WB  (OFF_W2 + 64*36)
#define OFF_ACT (OFF_WB + 64*36)     // 16832
// per-sub, 2 edges (words): xsh 0(2x288) xch 576(2x576) aoh 1728(2x576)
//   qvh 2880(2x1088) vpw 5056(2x768) xcf 6592(2x1088 f32)
//   qvf overlays qvh region: 2880(2x1088 f32)   [lifetimes disjoint]
#define SUBW 8768
#define SMEM_WORDS (OFF_ACT + 4*SUBW)

__device__ float g_hA[(size_t)NN * 512];
__device__ float g_hB[(size_t)NN * 512];
__device__ float g_inv[NN];
__device__ int   g_any;

__global__ void setup0_kernel() {
    size_t i = (size_t)blockIdx.x * blockDim.x + threadIdx.x;
    if (i == 0) g_any = 0;
    if (i < NN) g_inv[i] = 0.f;
    if (i < (size_t)NN * 128) ((float4*)g_hB)[i] = make_float4(0.f, 0.f, 0.f, 0.f);
}
__global__ void detect_kernel(const int* __restrict__ ei) {
    int i = blockIdx.x * blockDim.x + threadIdx.x;
    int v = 0;
    for (int k = i; k < EE; k += gridDim.x * blockDim.x) v |= ei[2 * k + 1];
    if (v) atomicOr(&g_any, 1);
}
__global__ void embed_kernel(const float* __restrict__ x, const float* __restrict__ nw,
                             const float* __restrict__ nb) {
    int i = blockIdx.x * blockDim.x + threadIdx.x;
    if (i < NN * 512) {
        int n = i >> 9, r = i & 511;
        g_hA[i] = x[n * 8 + (r >> 6)] * nw[r] + nb[r];
    }
}
__global__ void count_kernel(const int* __restrict__ ei) {
    int e = blockIdx.x * blockDim.x + threadIdx.x;
    if (e < EE) {
        int t = (g_any == 0) ? ei[2 * (EE + e)] : ei[EE + e];
        atomicAdd(&g_inv[t], 1.0f);
    }
}
__global__ void fin_cnt_kernel() {
    int i = blockIdx.x * blockDim.x + threadIdx.x;
    if (i < NN) g_inv[i] = 1.0f / fmaxf(g_inv[i], 1.0f);
}
__global__ void zeroA_kernel() {
    size_t i = (size_t)blockIdx.x * blockDim.x + threadIdx.x;
    if (i < (size_t)NN * 128) ((float4*)g_hA)[i] = make_float4(0.f, 0.f, 0.f, 0.f);
}

// ---- f16 mma helpers ----
__device__ __forceinline__ void mma_f16(float& c0, float& c1, float& c2, float& c3,
                                        unsigned a0, unsigned a1, unsigned a2, unsigned a3,
                                        unsigned b0, unsigned b1) {
    asm volatile(
        "mma.sync.aligned.m16n8k16.row.col.f32.f16.f16.f32 "
        "{%0,%1,%2,%3}, {%4,%5,%6,%7}, {%8,%9}, {%0,%1,%2,%3};\n"
        : "+f"(c0), "+f"(c1), "+f"(c2), "+f"(c3)
        : "r"(a0), "r"(a1), "r"(a2), "r"(a3), "r"(b0), "r"(b1));
}
__device__ __forceinline__ unsigned packh2(float hi, float lo) {
    unsigned d;
    asm("cvt.rn.f16x2.f32 %0, %1, %2;" : "=r"(d) : "f"(hi), "f"(lo));
    return d;
}
__device__ __forceinline__ void load_ah(unsigned a[4][4], const unsigned* __restrict__ X,
                                        int lane) {
    int row = lane >> 2, tg = lane & 3;
    const unsigned* p0 = X + row * 36 + tg;
    const unsigned* p1 = X + (row + 8) * 36 + tg;
    #pragma unroll
    for (int kc = 0; kc < 4; kc++) {
        a[kc][0] = p0[kc * 8];
        a[kc][1] = p1[kc * 8];
        a[kc][2] = p0[kc * 8 + 4];
        a[kc][3] = p1[kc * 8 + 4];
    }
}

// two-edge tile: one B load, two 4-MMA chains.
// EPI: 0 plain, 1 relu, 2 +residual. HOUT half2 out; FOUT f32 out.
template<int EPI, bool ROWS8, bool HOUT, bool FOUT>
__device__ __forceinline__ void gemm2(const unsigned a0[4][4], const unsigned a1[4][4],
                                      const unsigned* __restrict__ W,
                                      const float* __restrict__ bias, int jbase,
                                      unsigned* Ch0, unsigned* Ch1, int chw,
                                      float* Cf0, float* Cf1, int cfw,
                                      const float* R0, const float* R1, int rw, int lane) {
    int g = lane >> 2, tg = lane & 3;
    int col0 = jbase + 2 * tg;
    float2 bb = *(const float2*)(bias + col0);
    float d00 = bb.x, d01 = bb.y, d02 = bb.x, d03 = bb.y;
    float d10 = bb.x, d11 = bb.y, d12 = bb.x, d13 = bb.y;
    const unsigned* wr = W + (jbase + g) * 36 + tg;
    unsigned b0[4], b1[4];
    #pragma unroll
    for (int kc = 0; kc < 4; kc++) { b0[kc] = wr[kc * 8]; b1[kc] = wr[kc * 8 + 4]; }
    #pragma unroll
    for (int kc = 0; kc < 4; kc++)
        mma_f16(d00, d01, d02, d03, a0[kc][0], a0[kc][1], a0[kc][2], a0[kc][3], b0[kc], b1[kc]);
    #pragma unroll
    for (int kc = 0; kc < 4; kc++)
        mma_f16(d10, d11, d12, d13, a1[kc][0], a1[kc][1], a1[kc][2], a1[kc][3], b0[kc], b1[kc]);
    if (EPI == 2) {
        float2 r00 = *(const float2*)(R0 + g * rw + col0);
        float2 r01 = *(const float2*)(R0 + (g + 8) * rw + col0);
        float2 r10 = *(const float2*)(R1 + g * rw + col0);
        float2 r11 = *(const float2*)(R1 + (g + 8) * rw + col0);
        d00 += r00.x; d01 += r00.y; d02 += r01.x; d03 += r01.y;
        d10 += r10.x; d11 += r10.y; d12 += r11.x; d13 += r11.y;
    }
    if (EPI == 1) {
        d00 = fmaxf(d00, 0.f); d01 = fmaxf(d01, 0.f); d02 = fmaxf(d02, 0.f); d03 = fmaxf(d03, 0.f);
        d10 = fmaxf(d10, 0.f); d11 = fmaxf(d11, 0.f); d12 = fmaxf(d12, 0.f); d13 = fmaxf(d13, 0.f);
    }
    if (HOUT) {
        Ch0[g * chw + (jbase >> 1) + tg] = packh2(d01, d00);
        Ch1[g * chw + (jbase >> 1) + tg] = packh2(d11, d10);
        if (!ROWS8) {
            Ch0[(g + 8) * chw + (jbase >> 1) + tg] = packh2(d03, d02);
            Ch1[(g + 8) * chw + (jbase >> 1) + tg] = packh2(d13, d12);
        }
    }
    if (FOUT) {
        *(float2*)(Cf0 + g * cfw + col0) = make_float2(d00, d01);
        *(float2*)(Cf1 + g * cfw + col0) = make_float2(d10, d11);
        if (!ROWS8) {
            *(float2*)(Cf0 + (g + 8) * cfw + col0) = make_float2(d02, d03);
            *(float2*)(Cf1 + (g + 8) * cfw + col0) = make_float2(d12, d13);
        }
    }
}

#define SUBBAR() asm volatile("bar.sync %0, 128;" :: "r"(sub + 1) : "memory")
#define XSH(e) (subw + 0    + (e)*288)
#define XCH(e) (subw + 576  + (e)*576)
#define AOH(e) (subw + 1728 + (e)*576)
#define QVH(e) (subw + 2880 + (e)*1088)
#define VPW(e) (subw + 5056 + (e)*768)
#define XCF(e) ((float*)(subw + 6592 + (e)*1088))
#define QVF(e) ((float*)(subw + 2880 + (e)*1088))

__global__ void __launch_bounds__(512, 1)
edge_kernel(const int* __restrict__ ei, int dir,
            const float* __restrict__ bpw, const float* __restrict__ bpb,
            const float* __restrict__ ipw, const float* __restrict__ ipb,
            const float* __restrict__ opw, const float* __restrict__ opb,
            const float* __restrict__ ln1g, const float* __restrict__ ln1b,
            const float* __restrict__ ln2g, const float* __restrict__ ln2b,
            const float* __restrict__ w1,  const float* __restrict__ fb1,
            const float* __restrict__ w2,  const float* __restrict__ fb2) {
    extern __shared__ float sm[];
    unsigned* smw = (unsigned*)sm;
    float* s_b = sm;
    __half* whq = (__half*)(smw + OFF_WQ);
    __half* who = (__half*)(smw + OFF_WO);
    __half* wh1 = (__half*)(smw + OFF_W1);
    __half* wh2 = (__half*)(smw + OFF_W2);
    __half* whb = (__half*)(smw + OFF_WB);

    const float* hin  = dir ? g_hB : g_hA;
    float*       hout = dir ? g_hA : g_hB;
    const int tid = threadIdx.x;

    for (int i = tid; i < 192 * 64; i += 512)
        whq[(i >> 6) * 72 + (i & 63)] = __float2half_rn(ipw[i]);
    for (int i = tid; i < 64 * 64; i += 512) {
        int r = (i >> 6) * 72 + (i & 63);
        who[r] = __float2half_rn(opw[i]);
        wh1[r] = __float2half_rn(w1[i]);
        wh2[r] = __float2half_rn(w2[i]);
        whb[r] = __float2half_rn(bpw[i]);
    }
    for (int i = tid; i < 192; i += 512) s_b[i] = ipb[i];
    if (tid < 64) {
        s_b[192 + tid] = opb[tid];  s_b[256 + tid] = fb1[tid];
        s_b[320 + tid] = fb2[tid];  s_b[384 + tid] = ln1g[tid];
        s_b[448 + tid] = ln1b[tid]; s_b[512 + tid] = ln2g[tid];
        s_b[576 + tid] = ln2b[tid]; s_b[640 + tid] = bpb[tid];
    }
    __syncthreads();

    const int sub  = tid >> 7;
    const int st   = tid & 127;
    const int warp = st >> 5;
    const int lane = st & 31;
    const int g    = lane >> 2, tg = lane & 3;
    unsigned* subw = smw + OFF_ACT + sub * SUBW;

    const unsigned* Wq  = smw + OFF_WQ;
    const unsigned* Wo  = smw + OFF_WO;
    const unsigned* W1p = smw + OFF_W1;
    const unsigned* W2p = smw + OFF_W2;
    const unsigned* Wb  = smw + OFF_WB;

    const int is64 = (g_any == 0);
    const int r0 = st >> 4, d0 = (st & 15) << 2;
    const int stride8 = gridDim.x * 8;

    // prologue prefetch (2 edges)
    bool pv0, pv1; int pt0 = 0, pt1 = 0; float pc0 = 0.f, pc1 = 0.f;
    float4 pvi0 = make_float4(0,0,0,0), pvj0 = pvi0, pvi1 = pvi0, pvj1 = pvi0;
    {
        int e0 = blockIdx.x * 8 + sub * 2;
        pv0 = e0 < EE; pv1 = (e0 + 1) < EE;
        if (pv0) {
            int s0 = is64 ? ei[2 * e0] : ei[e0];
            pt0    = is64 ? ei[2 * (EE + e0)] : ei[EE + e0];
            pc0 = g_inv[pt0];
            pvi0 = *(const float4*)(hin + (size_t)pt0 * 512 + r0 * 64 + d0);
            pvj0 = *(const float4*)(hin + (size_t)s0  * 512 + r0 * 64 + d0);
        }
        if (pv1) {
            int e1 = e0 + 1;
            int s1 = is64 ? ei[2 * e1] : ei[e1];
            pt1    = is64 ? ei[2 * (EE + e1)] : ei[EE + e1];
            pc1 = g_inv[pt1];
            pvi1 = *(const float4*)(hin + (size_t)pt1 * 512 + r0 * 64 + d0);
            pvj1 = *(const float4*)(hin + (size_t)s1  * 512 + r0 * 64 + d0);
        }
    }

    for (int base = blockIdx.x * 8; base < EE; base += stride8) {
        const bool v0 = pv0, v1 = pv1;
        const int  t0i = pt0, t1i = pt1;
        const float c0i = pc0, c1i = pc1;

        // P0: commit gathers
        if (v0) {
            *(float4*)(XCF(0) + r0 * 68 + d0) = pvi0;
            int wb = r0 * 36 + (d0 >> 1);
            XCH(0)[wb]     = packh2(pvi0.y, pvi0.x);
            XCH(0)[wb + 1] = packh2(pvi0.w, pvi0.z);
            XSH(0)[wb]     = packh2(pvj0.y, pvj0.x);
            XSH(0)[wb + 1] = packh2(pvj0.w, pvj0.z);
        }
        if (v1) {
            *(float4*)(XCF(1) + r0 * 68 + d0) = pvi1;
            int wb = r0 * 36 + (d0 >> 1);
            XCH(1)[wb]     = packh2(pvi1.y, pvi1.x);
            XCH(1)[wb + 1] = packh2(pvi1.w, pvi1.z);
            XSH(1)[wb]     = packh2(pvj1.y, pvj1.x);
            XSH(1)[wb + 1] = packh2(pvj1.w, pvj1.z);
        }
        SUBBAR();

        // prefetch next iteration
        {
            int e0 = base + stride8 + sub * 2;
            pv0 = e0 < EE; pv1 = (e0 + 1) < EE;
            if (pv0) {
                int s0 = is64 ? ei[2 * e0] : ei[e0];
                pt0    = is64 ? ei[2 * (EE + e0)] : ei[EE + e0];
                pc0 = g_inv[pt0];
                pvi0 = *(const float4*)(hin + (size_t)pt0 * 512 + r0 * 64 + d0);
                pvj0 = *(const float4*)(hin + (size_t)s0  * 512 + r0 * 64 + d0);
            }
            if (pv1) {
                int e1 = e0 + 1;
                int s1 = is64 ? ei[2 * e1] : ei[e1];
                pt1    = is64 ? ei[2 * (EE + e1)] : ei[EE + e1];
                pc1 = g_inv[pt1];
                pvi1 = *(const float4*)(hin + (size_t)pt1 * 512 + r0 * 64 + d0);
                pvj1 = *(const float4*)(hin + (size_t)s1  * 512 + r0 * 64 + d0);
            }
        }

        // P1: bproj (both edges) -> rows 8..15 of XCH/XCF
        if (v0) {
            unsigned a0[4][4], a1[4][4];
            load_ah(a0, XSH(0), lane);
            load_ah(a1, XSH(1), lane);
            gemm2<0, true, true, true>(a0, a1, Wb, s_b + 640, warp * 16,
                XCH(0) + 8 * 36, XCH(1) + 8 * 36, 36,
                XCF(0) + 8 * 68, XCF(1) + 8 * 68, 68, 0, 0, 0, lane);
            gemm2<0, true, true, true>(a0, a1, Wb, s_b + 640, warp * 16 + 8,
                XCH(0) + 8 * 36, XCH(1) + 8 * 36, 36,
                XCF(0) + 8 * 68, XCF(1) + 8 * 68, 68, 0, 0, 0, lane);
        }
        SUBBAR();

        // P2: qkv (both edges share B)
        if (v0) {
            unsigned a0[4][4], a1[4][4];
            load_ah(a0, XCH(0), lane);
            load_ah(a1, XCH(1), lane);
            #pragma unroll
            for (int nt = 0; nt < 6; nt++) {
                int jb = warp * 48 + nt * 8;
                int col0 = jb + 2 * tg;
                float2 bb = *(const float2*)(s_b + col0);
                float d00 = bb.x, d01 = bb.y, d02 = bb.x, d03 = bb.y;
                float d10 = bb.x, d11 = bb.y, d12 = bb.x, d13 = bb.y;
                const unsigned* wr = Wq + (jb + g) * 36 + tg;
                unsigned b0[4], b1[4];
                #pragma unroll
                for (int kc = 0; kc < 4; kc++) { b0[kc] = wr[kc * 8]; b1[kc] = wr[kc * 8 + 4]; }
                #pragma unroll
                for (int kc = 0; kc < 4; kc++)
                    mma_f16(d00, d01, d02, d03, a0[kc][0], a0[kc][1], a0[kc][2], a0[kc][3], b0[kc], b1[kc]);
                #pragma unroll
                for (int kc = 0; kc < 4; kc++)
                    mma_f16(d10, d11, d12, d13, a1[kc][0], a1[kc][1], a1[kc][2], a1[kc][3], b0[kc], b1[kc]);
                if (jb < 128) {
                    QVH(0)[g * 68 + (jb >> 1) + tg]       = packh2(d01, d00);
                    QVH(0)[(g + 8) * 68 + (jb >> 1) + tg] = packh2(d03, d02);
                    QVH(1)[g * 68 + (jb >> 1) + tg]       = packh2(d11, d10);
                    QVH(1)[(g + 8) * 68 + (jb >> 1) + tg] = packh2(d13, d12);
                } else {
                    int dL = jb - 128 + 2 * tg;
                    __half* vp0 = (__half*)VPW(0);
                    __half* vp1 = (__half*)VPW(1);
                    vp0[dL * 24 + g]           = __float2half_rn(d00);
                    vp0[(dL + 1) * 24 + g]     = __float2half_rn(d01);
                    vp0[dL * 24 + g + 8]       = __float2half_rn(d02);
                    vp0[(dL + 1) * 24 + g + 8] = __float2half_rn(d03);
                    vp1[dL * 24 + g]           = __float2half_rn(d10);
                    vp1[(dL + 1) * 24 + g]     = __float2half_rn(d11);
                    vp1[dL * 24 + g + 8]       = __float2half_rn(d12);
                    vp1[(dL + 1) * 24 + g + 8] = __float2half_rn(d13);
                }
            }
        }
        SUBBAR();

        // P3: attention (warp = head), per edge
        if (v0) {
            #pragma unroll
            for (int e = 0; e < 2; e++) {
                const unsigned* qb = QVH(e) + warp * 8;
                const unsigned* kb = QVH(e) + 32 + warp * 8;
                unsigned a0 = qb[g * 68 + tg],     a1 = qb[(g + 8) * 68 + tg];
                unsigned a2 = qb[g * 68 + tg + 4], a3 = qb[(g + 8) * 68 + tg + 4];
                float s00 = 0, s01 = 0, s02 = 0, s03 = 0;
                float s10 = 0, s11 = 0, s12 = 0, s13 = 0;
                mma_f16(s00, s01, s02, s03, a0, a1, a2, a3,
                        kb[g * 68 + tg], kb[g * 68 + tg + 4]);
                mma_f16(s10, s11, s12, s13, a0, a1, a2, a3,
                        kb[(g + 8) * 68 + tg], kb[(g + 8) * 68 + tg + 4]);
                s00 *= 0.25f; s01 *= 0.25f; s02 *= 0.25f; s03 *= 0.25f;
                s10 *= 0.25f; s11 *= 0.25f; s12 *= 0.25f; s13 *= 0.25f;
                float m0 = fmaxf(fmaxf(s00, s01), fmaxf(s10, s11));
                float m1 = fmaxf(fmaxf(s02, s03), fmaxf(s12, s13));
                m0 = fmaxf(m0, __shfl_xor_sync(0xffffffffu, m0, 1));
                m0 = fmaxf(m0, __shfl_xor_sync(0xffffffffu, m0, 2));
                m1 = fmaxf(m1, __shfl_xor_sync(0xffffffffu, m1, 1));
                m1 = fmaxf(m1, __shfl_xor_sync(0xffffffffu, m1, 2));
                float e00 = __expf(s00 - m0), e01 = __expf(s01 - m0);
                float e10 = __expf(s10 - m0), e11 = __expf(s11 - m0);
                float e02 = __expf(s02 - m1), e03 = __expf(s03 - m1);
                float e12 = __expf(s12 - m1), e13 = __expf(s13 - m1);
                float t0 = (e00 + e01) + (e10 + e11);
                float t1 = (e02 + e03) + (e12 + e13);
                t0 += __shfl_xor_sync(0xffffffffu, t0, 1);
                t0 += __shfl_xor_sync(0xffffffffu, t0, 2);
                t1 += __shfl_xor_sync(0xffffffffu, t1, 1);
                t1 += __shfl_xor_sync(0xffffffffu, t1, 2);
                float r0s = 1.f / t0, r1s = 1.f / t1;
                unsigned ap0 = packh2(e01 * r0s, e00 * r0s);
                unsigned ap1 = packh2(e03 * r1s, e02 * r1s);
                unsigned ap2 = packh2(e11 * r0s, e10 * r0s);
                unsigned ap3 = packh2(e13 * r1s, e12 * r1s);
                const unsigned* vb = VPW(e) + warp * 192;
                unsigned* ao = AOH(e);
                #pragma unroll
                for (int jb2 = 0; jb2 < 2; jb2++) {
                    float c0 = 0, c1 = 0, c2 = 0, c3 = 0;
                    const unsigned* vr = vb + (jb2 * 8 + g) * 12 + tg;
                    mma_f16(c0, c1, c2, c3, ap0, ap1, ap2, ap3, vr[0], vr[4]);
                    ao[g * 36 + warp * 8 + jb2 * 4 + tg]       = packh2(c1, c0);
                    ao[(g + 8) * 36 + warp * 8 + jb2 * 4 + tg] = packh2(c3, c2);
                }
            }
        }
        SUBBAR();

        // P4: out_proj + residual -> QVF (f32)
        if (v0) {
            unsigned a0[4][4], a1[4][4];
            load_ah(a0, AOH(0), lane);
            load_ah(a1, AOH(1), lane);
            gemm2<2, false, false, true>(a0, a1, Wo, s_b + 192, warp * 16,
                0, 0, 0, QVF(0), QVF(1), 68, XCF(0), XCF(1), 68, lane);
            gemm2<2, false, false, true>(a0, a1, Wo, s_b + 192, warp * 16 + 8,
                0, 0, 0, QVF(0), QVF(1), 68, XCF(0), XCF(1), 68, lane);
        }
        SUBBAR();

        // LN1 (8 threads/row) per edge: QVF -> XCF + XCH
        if (v0) {
            #pragma unroll
            for (int e = 0; e < 2; e++) {
                float* qvfe = QVF(e);
                float* xcfe = XCF(e);
                unsigned* xche = XCH(e);
                int row = st >> 3, part = st & 7, ci = part * 8;
                const float4* p = (const float4*)(qvfe + row * 68 + ci);
                float4 u0 = p[0], u1 = p[1];
                float s = (u0.x + u0.y) + (u0.z + u0.w) + (u1.x + u1.y) + (u1.z + u1.w);
                s += __shfl_xor_sync(0xffffffffu, s, 1);
                s += __shfl_xor_sync(0xffffffffu, s, 2);
                s += __shfl_xor_sync(0xffffffffu, s, 4);
                float mu = s * 0.015625f;
                float t0 = u0.x - mu, t1 = u0.y - mu, t2 = u0.z - mu, t3 = u0.w - mu;
                float t4 = u1.x - mu, t5 = u1.y - mu, t6 = u1.z - mu, t7 = u1.w - mu;
                float v = t0*t0 + t1*t1 + t2*t2 + t3*t3 + t4*t4 + t5*t5 + t6*t6 + t7*t7;
                v += __shfl_xor_sync(0xffffffffu, v, 1);
                v += __shfl_xor_sync(0xffffffffu, v, 2);
                v += __shfl_xor_sync(0xffffffffu, v, 4);
                float rstd = rsqrtf(v * 0.015625f + 1e-5f);
                const float4 g0 = *(const float4*)(s_b + 384 + ci);
                const float4 g1 = *(const float4*)(s_b + 384 + ci + 4);
                const float4 b0 = *(const float4*)(s_b + 448 + ci);
                const float4 b1 = *(const float4*)(s_b + 448 + ci + 4);
                float o0 = t0 * rstd * g0.x + b0.x, o1 = t1 * rstd * g0.y + b0.y;
                float o2 = t2 * rstd * g0.z + b0.z, o3 = t3 * rstd * g0.w + b0.w;
                float o4 = t4 * rstd * g1.x + b1.x, o5 = t5 * rstd * g1.y + b1.y;
                float o6 = t6 * rstd * g1.z + b1.z, o7 = t7 * rstd * g1.w + b1.w;
                *(float4*)(xcfe + row * 68 + ci)     = make_float4(o0, o1, o2, o3);
                *(float4*)(xcfe + row * 68 + ci + 4) = make_float4(o4, o5, o6, o7);
                int wb = row * 36 + part * 4;
                xche[wb]     = packh2(o1, o0);
                xche[wb + 1] = packh2(o3, o2);
                xche[wb + 2] = packh2(o5, o4);
                xche[wb + 3] = packh2(o7, o6);
            }
        }
        SUBBAR();

        // P6: FF1 + relu -> AOH
        if (v0) {
            unsigned a0[4][4], a1[4][4];
            load_ah(a0, XCH(0), lane);
            load_ah(a1, XCH(1), lane);
            gemm2<1, false, true, false>(a0, a1, W1p, s_b + 256, warp * 16,
                AOH(0), AOH(1), 36, 0, 0, 0, 0, 0, 0, lane);
            gemm2<1, false, true, false>(a0, a1, W1p, s_b + 256, warp * 16 + 8,
                AOH(0), AOH(1), 36, 0, 0, 0, 0, 0, 0, lane);
        }
        SUBBAR();

        // P7: FF2 + residual -> QVF
        if (v0) {
            unsigned a0[4][4], a1[4][4];
            load_ah(a0, AOH(0), lane);
            load_ah(a1, AOH(1), lane);
            gemm2<2, false, false, true>(a0, a1, W2p, s_b + 320, warp * 16,
                0, 0, 0, QVF(0), QVF(1), 68, XCF(0), XCF(1), 68, lane);
            gemm2<2, false, false, true>(a0, a1, W2p, s_b + 320, warp * 16 + 8,
                0, 0, 0, QVF(0), QVF(1), 68, XCF(0), XCF(1), 68, lane);
        }
        SUBBAR();

        // LN2 (rows 0..7, 16 threads/row) + vector atomic scatter, per edge
        #pragma unroll
        for (int e = 0; e < 2; e++) {
            bool ve = e ? v1 : v0;
            if (!ve) continue;
            int tgte = e ? t1i : t0i;
            float ice = e ? c1i : c0i;
            float* qvfe = QVF(e);
            int row = st >> 4, part = st & 15, ci = part * 4;
            float4 u = *(const float4*)(qvfe + row * 68 + ci);
            float s = (u.x + u.y) + (u.z + u.w);
            s += __shfl_xor_sync(0xffffffffu, s, 1);
            s += __shfl_xor_sync(0xffffffffu, s, 2);
            s += __shfl_xor_sync(0xffffffffu, s, 4);
            s += __shfl_xor_sync(0xffffffffu, s, 8);
            float mu = s * 0.015625f;
            float t0 = u.x - mu, t1 = u.y - mu, t2 = u.z - mu, t3 = u.w - mu;
            float v = t0*t0 + t1*t1 + t2*t2 + t3*t3;
            v += __shfl_xor_sync(0xffffffffu, v, 1);
            v += __shfl_xor_sync(0xffffffffu, v, 2);
            v += __shfl_xor_sync(0xffffffffu, v, 4);
            v += __shfl_xor_sync(0xffffffffu, v, 8);
            float rstd = rsqrtf(v * 0.015625f + 1e-5f);
            const float4 gg = *(const float4*)(s_b + 512 + ci);
            const float4 bb = *(const float4*)(s_b + 576 + ci);
            float o0 = (t0 * rstd * gg.x + bb.x) * ice;
            float o1 = (t1 * rstd * gg.y + bb.y) * ice;
            float o2 = (t2 * rstd * gg.z + bb.z) * ice;
            float o3 = (t3 * rstd * gg.w + bb.w) * ice;
            float* dst = hout + (size_t)tgte * 512 + row * 64 + ci;
            asm volatile("red.global.add.v4.f32 [%0], {%1,%2,%3,%4};"
                         :: "l"(dst), "f"(o0), "f"(o1), "f"(o2), "f"(o3) : "memory");
        }
        // no trailing barrier: LN2 reads QVF; next writes to that region are P2
        // (two barriers away). P0/P1 touch XCF/XCH/XSH only.
    }
}

__global__ void out_kernel(const float* __restrict__ ow, const float* __restrict__ ob,
                           float* __restrict__ out) {
    __shared__ float shs[8][64];
    int w = threadIdx.x >> 5, lane = threadIdx.x & 31;
    int n = blockIdx.x * 8 + w;
    if (n >= NN) return;
    const float* hr = g_hA + (size_t)n * 512;
    float lo = 0.f, hi = 0.f;
    #pragma unroll
    for (int c = 0; c < 8; c++) { lo += hr[c * 64 + lane]; hi += hr[c * 64 + 32 + lane]; }
    shs[w][lane] = lo; shs[w][lane + 32] = hi;
    __syncwarp();
    float z = -1e30f;
    if (lane < 16) {
        float acc = 8.f * ob[lane];
        const float* wr = ow + lane * 64;
        #pragma unroll
        for (int d = 0; d < 64; d++) acc = fmaf(shs[w][d], wr[d], acc);
        z = acc;
    }
    float m = z;
    #pragma unroll
    for (int off = 8; off; off >>= 1) m = fmaxf(m, __shfl_xor_sync(0xffffffffu, m, off, 16));
    float p = __expf(z - m);
    float s = p;
    #pragma unroll
    for (int off = 8; off; off >>= 1) s += __shfl_xor_sync(0xffffffffu, s, off, 16);
    if (lane < 16) out[n * 16 + lane] = p / s;
}

extern "C" void kernel_launch(void* const* d_in, const int* in_sizes, int n_in,
                              void* d_out, int out_size) {
    const float* x    = (const float*)d_in[0];
    const int*   ei   = (const int*)d_in[1];
    const float* numw = (const float*)d_in[2];
    const float* numb = (const float*)d_in[3];
    const float* bpw  = (const float*)d_in[4];
    const float* bpb  = (const float*)d_in[5];
    const float* ipw  = (const float*)d_in[6];
    const float* ipb  = (const float*)d_in[7];
    const float* opw  = (const float*)d_in[8];
    const float* opb  = (const float*)d_in[9];
    const float* g1   = (const float*)d_in[10];
    const float* b1   = (const float*)d_in[11];
    const float* g2   = (const float*)d_in[12];
    const float* b2   = (const float*)d_in[13];
    const float* w1   = (const float*)d_in[14];
    const float* fb1  = (const float*)d_in[15];
    const float* w2   = (const float*)d_in[16];
    const float* fb2  = (const float*)d_in[17];
    const float* ow   = (const float*)d_in[18];
    const float* ob   = (const float*)d_in[19];
    float* out = (float*)d_out;

    const int SMEM_BYTES = SMEM_WORDS * 4;
    cudaFuncSetAttribute(edge_kernel, cudaFuncAttributeMaxDynamicSharedMemorySize, SMEM_BYTES);

    int dev = 0, sms = 148;
    cudaGetDevice(&dev);
    cudaDeviceGetAttribute(&sms, cudaDevAttrMultiProcessorCount, dev);

    setup0_kernel<<<(NN * 128 + 255) / 256, 256>>>();
    detect_kernel<<<256, 256>>>(ei);
    embed_kernel<<<(NN * 512 + 255) / 256, 256>>>(x, numw, numb);
    count_kernel<<<(EE + 255) / 256, 256>>>(ei);
    fin_cnt_kernel<<<(NN + 255) / 256, 256>>>();

    edge_kernel<<<sms, 512, SMEM_BYTES>>>(ei, 0,
        bpw, bpb, ipw, ipb, opw, opb, g1, b1, g2, b2, w1, fb1, w2, fb2);

    zeroA_kernel<<<(NN * 128 + 255) / 256, 256>>>();
    edge_kernel<<<sms, 512, SMEM_BYTES>>>(ei, 1,
        bpw + 64 * 64, bpb + 64, ipw + 192 * 64, ipb + 192, opw + 64 * 64, opb + 64,
        g1 + 64, b1 + 64, g2 + 64, b2 + 64,
        w1 + 64 * 64, fb1 + 64, w2 + 64 * 64, fb2 + 64);

    out_kernel<<<(NN + 7) / 8, 256>>>(ow, ob, out);
}

// round 12
// speedup vs baseline: 2.7676x; 1.1121x over previous
#include <cuda_runtime.h>
#include <cuda_fp16.h>

#define NN 50000
#define EE 100000

// word offsets in dynamic smem
#define OFF_WQ  704
#define OFF_WO  (OFF_WQ + 192*36)
#define OFF_W1  (OFF_WO + 64*36)
#define OFF_W2  (OFF_W1 + 64*36)
#define OFF_WB  (OFF_W2 + 64*36)
#define OFF_ACT (OFF_WB + 64*36)     // 16832
// per-sub, 2 edges (words): xsh 0(2x288) xch 576(2x576) aoh 1728(2x576)
//   qvh 2880(2x1088) vpw 5056(2x768) xcf 6592(2x1088 f32) pp 8768(2x128 f32)
#define SUBW 9024
#define SMEM_WORDS (OFF_ACT + 4*SUBW)

__device__ float g_hA[(size_t)NN * 512];
__device__ float g_hB[(size_t)NN * 512];
__device__ float g_inv[NN];
__device__ int   g_any;

__global__ void setup0_kernel() {
    size_t i = (size_t)blockIdx.x * blockDim.x + threadIdx.x;
    if (i == 0) g_any = 0;
    if (i < NN) g_inv[i] = 0.f;
    if (i < (size_t)NN * 128) ((float4*)g_hB)[i] = make_float4(0.f, 0.f, 0.f, 0.f);
}
__global__ void detect_kernel(const int* __restrict__ ei) {
    int i = blockIdx.x * blockDim.x + threadIdx.x;
    int v = 0;
    for (int k = i; k < EE; k += gridDim.x * blockDim.x) v |= ei[2 * k + 1];
    if (v) atomicOr(&g_any, 1);
}
__global__ void embed_kernel(const float* __restrict__ x, const float* __restrict__ nw,
                             const float* __restrict__ nb) {
    int i = blockIdx.x * blockDim.x + threadIdx.x;
    if (i < NN * 512) {
        int n = i >> 9, r = i & 511;
        g_hA[i] = x[n * 8 + (r >> 6)] * nw[r] + nb[r];
    }
}
__global__ void count_kernel(const int* __restrict__ ei) {
    int e = blockIdx.x * blockDim.x + threadIdx.x;
    if (e < EE) {
        int t = (g_any == 0) ? ei[2 * (EE + e)] : ei[EE + e];
        atomicAdd(&g_inv[t], 1.0f);
    }
}
__global__ void fin_cnt_kernel() {
    int i = blockIdx.x * blockDim.x + threadIdx.x;
    if (i < NN) g_inv[i] = 1.0f / fmaxf(g_inv[i], 1.0f);
}
__global__ void zeroA_kernel() {
    size_t i = (size_t)blockIdx.x * blockDim.x + threadIdx.x;
    if (i < (size_t)NN * 128) ((float4*)g_hA)[i] = make_float4(0.f, 0.f, 0.f, 0.f);
}

// ---- f16 mma helpers ----
__device__ __forceinline__ void mma_f16(float& c0, float& c1, float& c2, float& c3,
                                        unsigned a0, unsigned a1, unsigned a2, unsigned a3,
                                        unsigned b0, unsigned b1) {
    asm volatile(
        "mma.sync.aligned.m16n8k16.row.col.f32.f16.f16.f32 "
        "{%0,%1,%2,%3}, {%4,%5,%6,%7}, {%8,%9}, {%0,%1,%2,%3};\n"
        : "+f"(c0), "+f"(c1), "+f"(c2), "+f"(c3)
        : "r"(a0), "r"(a1), "r"(a2), "r"(a3), "r"(b0), "r"(b1));
}
__device__ __forceinline__ unsigned packh2(float hi, float lo) {
    unsigned d;
    asm("cvt.rn.f16x2.f32 %0, %1, %2;" : "=r"(d) : "f"(hi), "f"(lo));
    return d;
}
__device__ __forceinline__ void load_ah(unsigned a[4][4], const unsigned* __restrict__ X,
                                        int lane) {
    int row = lane >> 2, tg = lane & 3;
    const unsigned* p0 = X + row * 36 + tg;
    const unsigned* p1 = X + (row + 8) * 36 + tg;
    #pragma unroll
    for (int kc = 0; kc < 4; kc++) {
        a[kc][0] = p0[kc * 8];
        a[kc][1] = p1[kc * 8];
        a[kc][2] = p0[kc * 8 + 4];
        a[kc][3] = p1[kc * 8 + 4];
    }
}

// two-edge tile: one B load, two 4-MMA chains.
// EPI: 0 plain, 1 relu, 2 +residual. HOUT half2 out; FOUT f32 out.
template<int EPI, bool ROWS8, bool HOUT, bool FOUT>
__device__ __forceinline__ void gemm2(const unsigned a0[4][4], const unsigned a1[4][4],
                                      const unsigned* __restrict__ W,
                                      const float* __restrict__ bias, int jbase,
                                      unsigned* Ch0, unsigned* Ch1, int chw,
                                      float* Cf0, float* Cf1, int cfw,
                                      const float* R0, const float* R1, int rw, int lane) {
    int g = lane >> 2, tg = lane & 3;
    int col0 = jbase + 2 * tg;
    float2 bb = *(const float2*)(bias + col0);
    float d00 = bb.x, d01 = bb.y, d02 = bb.x, d03 = bb.y;
    float d10 = bb.x, d11 = bb.y, d12 = bb.x, d13 = bb.y;
    const unsigned* wr = W + (jbase + g) * 36 + tg;
    unsigned b0[4], b1[4];
    #pragma unroll
    for (int kc = 0; kc < 4; kc++) { b0[kc] = wr[kc * 8]; b1[kc] = wr[kc * 8 + 4]; }
    #pragma unroll
    for (int kc = 0; kc < 4; kc++)
        mma_f16(d00, d01, d02, d03, a0[kc][0], a0[kc][1], a0[kc][2], a0[kc][3], b0[kc], b1[kc]);
    #pragma unroll
    for (int kc = 0; kc < 4; kc++)
        mma_f16(d10, d11, d12, d13, a1[kc][0], a1[kc][1], a1[kc][2], a1[kc][3], b0[kc], b1[kc]);
    if (EPI == 2) {
        float2 r00 = *(const float2*)(R0 + g * rw + col0);
        float2 r01 = *(const float2*)(R0 + (g + 8) * rw + col0);
        float2 r10 = *(const float2*)(R1 + g * rw + col0);
        float2 r11 = *(const float2*)(R1 + (g + 8) * rw + col0);
        d00 += r00.x; d01 += r00.y; d02 += r01.x; d03 += r01.y;
        d10 += r10.x; d11 += r10.y; d12 += r11.x; d13 += r11.y;
    }
    if (EPI == 1) {
        d00 = fmaxf(d00, 0.f); d01 = fmaxf(d01, 0.f); d02 = fmaxf(d02, 0.f); d03 = fmaxf(d03, 0.f);
        d10 = fmaxf(d10, 0.f); d11 = fmaxf(d11, 0.f); d12 = fmaxf(d12, 0.f); d13 = fmaxf(d13, 0.f);
    }
    if (HOUT) {
        Ch0[g * chw + (jbase >> 1) + tg] = packh2(d01, d00);
        Ch1[g * chw + (jbase >> 1) + tg] = packh2(d11, d10);
        if (!ROWS8) {
            Ch0[(g + 8) * chw + (jbase >> 1) + tg] = packh2(d03, d02);
            Ch1[(g + 8) * chw + (jbase >> 1) + tg] = packh2(d13, d12);
        }
    }
    if (FOUT) {
        *(float2*)(Cf0 + g * cfw + col0) = make_float2(d00, d01);
        *(float2*)(Cf1 + g * cfw + col0) = make_float2(d10, d11);
        if (!ROWS8) {
            *(float2*)(Cf0 + (g + 8) * cfw + col0) = make_float2(d02, d03);
            *(float2*)(Cf1 + (g + 8) * cfw + col0) = make_float2(d12, d13);
        }
    }
}

#define SUBBAR() asm volatile("bar.sync %0, 128;" :: "r"(sub + 1) : "memory")
#define XSH(e) (subw + 0    + (e)*288)
#define XCH(e) (subw + 576  + (e)*576)
#define AOH(e) (subw + 1728 + (e)*576)
#define QVH(e) (subw + 2880 + (e)*1088)
#define VPW(e) (subw + 5056 + (e)*768)
#define XCF(e) ((float*)(subw + 6592 + (e)*1088))
#define PP(e)  ((float*)(subw + 8768 + (e)*128))

__global__ void __launch_bounds__(512, 1)
edge_kernel(const int* __restrict__ ei, int dir,
            const float* __restrict__ bpw, const float* __restrict__ bpb,
            const float* __restrict__ ipw, const float* __restrict__ ipb,
            const float* __restrict__ opw, const float* __restrict__ opb,
            const float* __restrict__ ln1g, const float* __restrict__ ln1b,
            const float* __restrict__ ln2g, const float* __restrict__ ln2b,
            const float* __restrict__ w1,  const float* __restrict__ fb1,
            const float* __restrict__ w2,  const float* __restrict__ fb2) {
    extern __shared__ float sm[];
    unsigned* smw = (unsigned*)sm;
    float* s_b = sm;
    __half* whq = (__half*)(smw + OFF_WQ);
    __half* who = (__half*)(smw + OFF_WO);
    __half* wh1 = (__half*)(smw + OFF_W1);
    __half* wh2 = (__half*)(smw + OFF_W2);
    __half* whb = (__half*)(smw + OFF_WB);

    const float* hin  = dir ? g_hB : g_hA;
    float*       hout = dir ? g_hA : g_hB;
    const int tid = threadIdx.x;

    for (int i = tid; i < 192 * 64; i += 512)
        whq[(i >> 6) * 72 + (i & 63)] = __float2half_rn(ipw[i]);
    for (int i = tid; i < 64 * 64; i += 512) {
        int r = (i >> 6) * 72 + (i & 63);
        who[r] = __float2half_rn(opw[i]);
        wh1[r] = __float2half_rn(w1[i]);
        wh2[r] = __float2half_rn(w2[i]);
        whb[r] = __float2half_rn(bpw[i]);
    }
    for (int i = tid; i < 192; i += 512) s_b[i] = ipb[i];
    if (tid < 64) {
        s_b[192 + tid] = opb[tid];  s_b[256 + tid] = fb1[tid];
        s_b[320 + tid] = fb2[tid];  s_b[384 + tid] = ln1g[tid];
        s_b[448 + tid] = ln1b[tid]; s_b[512 + tid] = ln2g[tid];
        s_b[576 + tid] = ln2b[tid]; s_b[640 + tid] = bpb[tid];
    }
    __syncthreads();

    const int sub  = tid >> 7;
    const int st   = tid & 127;
    const int warp = st >> 5;
    const int lane = st & 31;
    const int g    = lane >> 2, tg = lane & 3;
    unsigned* subw = smw + OFF_ACT + sub * SUBW;

    const unsigned* Wq  = smw + OFF_WQ;
    const unsigned* Wo  = smw + OFF_WO;
    const unsigned* W1p = smw + OFF_W1;
    const unsigned* W2p = smw + OFF_W2;
    const unsigned* Wb  = smw + OFF_WB;

    const int is64 = (g_any == 0);
    const int r0 = st >> 4, d0 = (st & 15) << 2;
    const int stride8 = gridDim.x * 8;

    // prologue prefetch (2 edges)
    bool pv0, pv1; int pt0 = 0, pt1 = 0; float pc0 = 0.f, pc1 = 0.f;
    float4 pvi0 = make_float4(0,0,0,0), pvj0 = pvi0, pvi1 = pvi0, pvj1 = pvi0;
    {
        int e0 = blockIdx.x * 8 + sub * 2;
        pv0 = e0 < EE; pv1 = (e0 + 1) < EE;
        if (pv0) {
            int s0 = is64 ? ei[2 * e0] : ei[e0];
            pt0    = is64 ? ei[2 * (EE + e0)] : ei[EE + e0];
            pc0 = g_inv[pt0];
            pvi0 = *(const float4*)(hin + (size_t)pt0 * 512 + r0 * 64 + d0);
            pvj0 = *(const float4*)(hin + (size_t)s0  * 512 + r0 * 64 + d0);
        }
        if (pv1) {
            int e1 = e0 + 1;
            int s1 = is64 ? ei[2 * e1] : ei[e1];
            pt1    = is64 ? ei[2 * (EE + e1)] : ei[EE + e1];
            pc1 = g_inv[pt1];
            pvi1 = *(const float4*)(hin + (size_t)pt1 * 512 + r0 * 64 + d0);
            pvj1 = *(const float4*)(hin + (size_t)s1  * 512 + r0 * 64 + d0);
        }
    }

    for (int base = blockIdx.x * 8; base < EE; base += stride8) {
        const bool v0 = pv0, v1 = pv1;
        const int  t0i = pt0, t1i = pt1;
        const float c0i = pc0, c1i = pc1;

        // P0: commit gathers
        if (v0) {
            *(float4*)(XCF(0) + r0 * 68 + d0) = pvi0;
            int wb = r0 * 36 + (d0 >> 1);
            XCH(0)[wb]     = packh2(pvi0.y, pvi0.x);
            XCH(0)[wb + 1] = packh2(pvi0.w, pvi0.z);
            XSH(0)[wb]     = packh2(pvj0.y, pvj0.x);
            XSH(0)[wb + 1] = packh2(pvj0.w, pvj0.z);
        }
        if (v1) {
            *(float4*)(XCF(1) + r0 * 68 + d0) = pvi1;
            int wb = r0 * 36 + (d0 >> 1);
            XCH(1)[wb]     = packh2(pvi1.y, pvi1.x);
            XCH(1)[wb + 1] = packh2(pvi1.w, pvi1.z);
            XSH(1)[wb]     = packh2(pvj1.y, pvj1.x);
            XSH(1)[wb + 1] = packh2(pvj1.w, pvj1.z);
        }
        SUBBAR();

        // prefetch next iteration
        {
            int e0 = base + stride8 + sub * 2;
            pv0 = e0 < EE; pv1 = (e0 + 1) < EE;
            if (pv0) {
                int s0 = is64 ? ei[2 * e0] : ei[e0];
                pt0    = is64 ? ei[2 * (EE + e0)] : ei[EE + e0];
                pc0 = g_inv[pt0];
                pvi0 = *(const float4*)(hin + (size_t)pt0 * 512 + r0 * 64 + d0);
                pvj0 = *(const float4*)(hin + (size_t)s0  * 512 + r0 * 64 + d0);
            }
            if (pv1) {
                int e1 = e0 + 1;
                int s1 = is64 ? ei[2 * e1] : ei[e1];
                pt1    = is64 ? ei[2 * (EE + e1)] : ei[EE + e1];
                pc1 = g_inv[pt1];
                pvi1 = *(const float4*)(hin + (size_t)pt1 * 512 + r0 * 64 + d0);
                pvj1 = *(const float4*)(hin + (size_t)s1  * 512 + r0 * 64 + d0);
            }
        }

        // P1: bproj (both edges) -> rows 8..15 of XCH/XCF
        if (v0) {
            unsigned a0[4][4], a1[4][4];
            load_ah(a0, XSH(0), lane);
            load_ah(a1, XSH(1), lane);
            gemm2<0, true, true, true>(a0, a1, Wb, s_b + 640, warp * 16,
                XCH(0) + 8 * 36, XCH(1) + 8 * 36, 36,
                XCF(0) + 8 * 68, XCF(1) + 8 * 68, 68, 0, 0, 0, lane);
            gemm2<0, true, true, true>(a0, a1, Wb, s_b + 640, warp * 16 + 8,
                XCH(0) + 8 * 36, XCH(1) + 8 * 36, 36,
                XCF(0) + 8 * 68, XCF(1) + 8 * 68, 68, 0, 0, 0, lane);
        }
        SUBBAR();

        // P2: qkv (both edges share B); V transposed into vpw
        if (v0) {
            unsigned a0[4][4], a1[4][4];
            load_ah(a0, XCH(0), lane);
            load_ah(a1, XCH(1), lane);
            #pragma unroll
            for (int nt = 0; nt < 6; nt++) {
                int jb = warp * 48 + nt * 8;
                int col0 = jb + 2 * tg;
                float2 bb = *(const float2*)(s_b + col0);
                float d00 = bb.x, d01 = bb.y, d02 = bb.x, d03 = bb.y;
                float d10 = bb.x, d11 = bb.y, d12 = bb.x, d13 = bb.y;
                const unsigned* wr = Wq + (jb + g) * 36 + tg;
                unsigned b0[4], b1[4];
                #pragma unroll
                for (int kc = 0; kc < 4; kc++) { b0[kc] = wr[kc * 8]; b1[kc] = wr[kc * 8 + 4]; }
                #pragma unroll
                for (int kc = 0; kc < 4; kc++)
                    mma_f16(d00, d01, d02, d03, a0[kc][0], a0[kc][1], a0[kc][2], a0[kc][3], b0[kc], b1[kc]);
                #pragma unroll
                for (int kc = 0; kc < 4; kc++)
                    mma_f16(d10, d11, d12, d13, a1[kc][0], a1[kc][1], a1[kc][2], a1[kc][3], b0[kc], b1[kc]);
                if (jb < 128) {
                    QVH(0)[g * 68 + (jb >> 1) + tg]       = packh2(d01, d00);
                    QVH(0)[(g + 8) * 68 + (jb >> 1) + tg] = packh2(d03, d02);
                    QVH(1)[g * 68 + (jb >> 1) + tg]       = packh2(d11, d10);
                    QVH(1)[(g + 8) * 68 + (jb >> 1) + tg] = packh2(d13, d12);
                } else {
                    int dL = jb - 128 + 2 * tg;
                    __half* vp0 = (__half*)VPW(0);
                    __half* vp1 = (__half*)VPW(1);
                    vp0[dL * 24 + g]           = __float2half_rn(d00);
                    vp0[(dL + 1) * 24 + g]     = __float2half_rn(d01);
                    vp0[dL * 24 + g + 8]       = __float2half_rn(d02);
                    vp0[(dL + 1) * 24 + g + 8] = __float2half_rn(d03);
                    vp1[dL * 24 + g]           = __float2half_rn(d10);
                    vp1[(dL + 1) * 24 + g]     = __float2half_rn(d11);
                    vp1[dL * 24 + g + 8]       = __float2half_rn(d12);
                    vp1[(dL + 1) * 24 + g + 8] = __float2half_rn(d13);
                }
            }
        }
        SUBBAR();

        // P3: attention (warp = head), P in registers
        if (v0) {
            #pragma unroll
            for (int e = 0; e < 2; e++) {
                const unsigned* qb = QVH(e) + warp * 8;
                const unsigned* kb = QVH(e) + 32 + warp * 8;
                unsigned a0 = qb[g * 68 + tg],     a1 = qb[(g + 8) * 68 + tg];
                unsigned a2 = qb[g * 68 + tg + 4], a3 = qb[(g + 8) * 68 + tg + 4];
                float s00 = 0, s01 = 0, s02 = 0, s03 = 0;
                float s10 = 0, s11 = 0, s12 = 0, s13 = 0;
                mma_f16(s00, s01, s02, s03, a0, a1, a2, a3,
                        kb[g * 68 + tg], kb[g * 68 + tg + 4]);
                mma_f16(s10, s11, s12, s13, a0, a1, a2, a3,
                        kb[(g + 8) * 68 + tg], kb[(g + 8) * 68 + tg + 4]);
                s00 *= 0.25f; s01 *= 0.25f; s02 *= 0.25f; s03 *= 0.25f;
                s10 *= 0.25f; s11 *= 0.25f; s12 *= 0.25f; s13 *= 0.25f;
                float m0 = fmaxf(fmaxf(s00, s01), fmaxf(s10, s11));
                float m1 = fmaxf(fmaxf(s02, s03), fmaxf(s12, s13));
                m0 = fmaxf(m0, __shfl_xor_sync(0xffffffffu, m0, 1));
                m0 = fmaxf(m0, __shfl_xor_sync(0xffffffffu, m0, 2));
                m1 = fmaxf(m1, __shfl_xor_sync(0xffffffffu, m1, 1));
                m1 = fmaxf(m1, __shfl_xor_sync(0xffffffffu, m1, 2));
                float e00 = __expf(s00 - m0), e01 = __expf(s01 - m0);
                float e10 = __expf(s10 - m0), e11 = __expf(s11 - m0);
                float e02 = __expf(s02 - m1), e03 = __expf(s03 - m1);
                float e12 = __expf(s12 - m1), e13 = __expf(s13 - m1);
                float t0 = (e00 + e01) + (e10 + e11);
                float t1 = (e02 + e03) + (e12 + e13);
                t0 += __shfl_xor_sync(0xffffffffu, t0, 1);
                t0 += __shfl_xor_sync(0xffffffffu, t0, 2);
                t1 += __shfl_xor_sync(0xffffffffu, t1, 1);
                t1 += __shfl_xor_sync(0xffffffffu, t1, 2);
                float r0s = 1.f / t0, r1s = 1.f / t1;
                unsigned ap0 = packh2(e01 * r0s, e00 * r0s);
                unsigned ap1 = packh2(e03 * r1s, e02 * r1s);
                unsigned ap2 = packh2(e11 * r0s, e10 * r0s);
                unsigned ap3 = packh2(e13 * r1s, e12 * r1s);
                const unsigned* vb = VPW(e) + warp * 192;
                unsigned* ao = AOH(e);
                #pragma unroll
                for (int jb2 = 0; jb2 < 2; jb2++) {
                    float c0 = 0, c1 = 0, c2 = 0, c3 = 0;
                    const unsigned* vr = vb + (jb2 * 8 + g) * 12 + tg;
                    mma_f16(c0, c1, c2, c3, ap0, ap1, ap2, ap3, vr[0], vr[4]);
                    ao[g * 36 + warp * 8 + jb2 * 4 + tg]       = packh2(c1, c0);
                    ao[(g + 8) * 36 + warp * 8 + jb2 * 4 + tg] = packh2(c3, c2);
                }
            }
        }
        SUBBAR();

        // P4: out_proj + residual, register-resident; emit LN1 partials
        float p4[2][8];
        if (v0) {
            unsigned a0[4][4], a1[4][4];
            load_ah(a0, AOH(0), lane);
            load_ah(a1, AOH(1), lane);
            #pragma unroll
            for (int jt = 0; jt < 2; jt++) {
                int jb = warp * 16 + jt * 8;
                int col0 = jb + 2 * tg;
                float2 bb = *(const float2*)(s_b + 192 + col0);
                float d00 = bb.x, d01 = bb.y, d02 = bb.x, d03 = bb.y;
                float d10 = bb.x, d11 = bb.y, d12 = bb.x, d13 = bb.y;
                const unsigned* wr = Wo + (jb + g) * 36 + tg;
                unsigned b0[4], b1[4];
                #pragma unroll
                for (int kc = 0; kc < 4; kc++) { b0[kc] = wr[kc * 8]; b1[kc] = wr[kc * 8 + 4]; }
                #pragma unroll
                for (int kc = 0; kc < 4; kc++)
                    mma_f16(d00, d01, d02, d03, a0[kc][0], a0[kc][1], a0[kc][2], a0[kc][3], b0[kc], b1[kc]);
                #pragma unroll
                for (int kc = 0; kc < 4; kc++)
                    mma_f16(d10, d11, d12, d13, a1[kc][0], a1[kc][1], a1[kc][2], a1[kc][3], b0[kc], b1[kc]);
                float2 r00 = *(const float2*)(XCF(0) + g * 68 + col0);
                float2 r01 = *(const float2*)(XCF(0) + (g + 8) * 68 + col0);
                float2 r10 = *(const float2*)(XCF(1) + g * 68 + col0);
                float2 r11 = *(const float2*)(XCF(1) + (g + 8) * 68 + col0);
                p4[0][jt * 4 + 0] = d00 + r00.x; p4[0][jt * 4 + 1] = d01 + r00.y;
                p4[0][jt * 4 + 2] = d02 + r01.x; p4[0][jt * 4 + 3] = d03 + r01.y;
                p4[1][jt * 4 + 0] = d10 + r10.x; p4[1][jt * 4 + 1] = d11 + r10.y;
                p4[1][jt * 4 + 2] = d12 + r11.x; p4[1][jt * 4 + 3] = d13 + r11.y;
            }
            #pragma unroll
            for (int e = 0; e < 2; e++) {
                float sg  = (p4[e][0] + p4[e][1]) + (p4[e][4] + p4[e][5]);
                float sg8 = (p4[e][2] + p4[e][3]) + (p4[e][6] + p4[e][7]);
                float qg  = p4[e][0]*p4[e][0] + p4[e][1]*p4[e][1] + p4[e][4]*p4[e][4] + p4[e][5]*p4[e][5];
                float qg8 = p4[e][2]*p4[e][2] + p4[e][3]*p4[e][3] + p4[e][6]*p4[e][6] + p4[e][7]*p4[e][7];
                sg  += __shfl_xor_sync(0xffffffffu, sg, 1);  sg  += __shfl_xor_sync(0xffffffffu, sg, 2);
                sg8 += __shfl_xor_sync(0xffffffffu, sg8, 1); sg8 += __shfl_xor_sync(0xffffffffu, sg8, 2);
                qg  += __shfl_xor_sync(0xffffffffu, qg, 1);  qg  += __shfl_xor_sync(0xffffffffu, qg, 2);
                qg8 += __shfl_xor_sync(0xffffffffu, qg8, 1); qg8 += __shfl_xor_sync(0xffffffffu, qg8, 2);
                if (tg == 0) {
                    float* ppe = PP(e);
                    ppe[g * 8 + warp]           = sg;
                    ppe[g * 8 + 4 + warp]       = qg;
                    ppe[(g + 8) * 8 + warp]     = sg8;
                    ppe[(g + 8) * 8 + 4 + warp] = qg8;
                }
            }
        }
        SUBBAR();

        // LN1 finish: combine partials, normalize registers, write XCF + XCH
        if (v0) {
            #pragma unroll
            for (int e = 0; e < 2; e++) {
                float* ppe = PP(e);
                float4 sx  = *(const float4*)(ppe + g * 8);
                float4 sq  = *(const float4*)(ppe + g * 8 + 4);
                float4 sx8 = *(const float4*)(ppe + (g + 8) * 8);
                float4 sq8 = *(const float4*)(ppe + (g + 8) * 8 + 4);
                float mu   = ((sx.x + sx.y) + (sx.z + sx.w)) * 0.015625f;
                float ex2  = ((sq.x + sq.y) + (sq.z + sq.w)) * 0.015625f;
                float mu8  = ((sx8.x + sx8.y) + (sx8.z + sx8.w)) * 0.015625f;
                float ex28 = ((sq8.x + sq8.y) + (sq8.z + sq8.w)) * 0.015625f;
                float rstd  = rsqrtf(ex2 - mu * mu + 1e-5f);
                float rstd8 = rsqrtf(ex28 - mu8 * mu8 + 1e-5f);
                #pragma unroll
                for (int jt = 0; jt < 2; jt++) {
                    int jb = warp * 16 + jt * 8;
                    int col0 = jb + 2 * tg;
                    float2 gg = *(const float2*)(s_b + 384 + col0);
                    float2 be = *(const float2*)(s_b + 448 + col0);
                    float o0 = (p4[e][jt * 4 + 0] - mu) * rstd * gg.x + be.x;
                    float o1 = (p4[e][jt * 4 + 1] - mu) * rstd * gg.y + be.y;
                    float o2 = (p4[e][jt * 4 + 2] - mu8) * rstd8 * gg.x + be.x;
                    float o3 = (p4[e][jt * 4 + 3] - mu8) * rstd8 * gg.y + be.y;
                    *(float2*)(XCF(e) + g * 68 + col0)       = make_float2(o0, o1);
                    *(float2*)(XCF(e) + (g + 8) * 68 + col0) = make_float2(o2, o3);
                    XCH(e)[g * 36 + (jb >> 1) + tg]       = packh2(o1, o0);
                    XCH(e)[(g + 8) * 36 + (jb >> 1) + tg] = packh2(o3, o2);
                }
            }
        }
        SUBBAR();

        // P6: FF1 + relu -> AOH
        if (v0) {
            unsigned a0[4][4], a1[4][4];
            load_ah(a0, XCH(0), lane);
            load_ah(a1, XCH(1), lane);
            gemm2<1, false, true, false>(a0, a1, W1p, s_b + 256, warp * 16,
                AOH(0), AOH(1), 36, 0, 0, 0, 0, 0, 0, lane);
            gemm2<1, false, true, false>(a0, a1, W1p, s_b + 256, warp * 16 + 8,
                AOH(0), AOH(1), 36, 0, 0, 0, 0, 0, 0, lane);
        }
        SUBBAR();

        // P7: FF2 + residual (rows 0..7 only), register-resident; LN2 partials
        float p7[2][4];
        if (v0) {
            unsigned a0[4][4], a1[4][4];
            load_ah(a0, AOH(0), lane);
            load_ah(a1, AOH(1), lane);
            #pragma unroll
            for (int jt = 0; jt < 2; jt++) {
                int jb = warp * 16 + jt * 8;
                int col0 = jb + 2 * tg;
                float2 bb = *(const float2*)(s_b + 320 + col0);
                float d00 = bb.x, d01 = bb.y, d02 = bb.x, d03 = bb.y;
                float d10 = bb.x, d11 = bb.y, d12 = bb.x, d13 = bb.y;
                const unsigned* wr = W2p + (jb + g) * 36 + tg;
                unsigned b0[4], b1[4];
                #pragma unroll
                for (int kc = 0; kc < 4; kc++) { b0[kc] = wr[kc * 8]; b1[kc] = wr[kc * 8 + 4]; }
                #pragma unroll
                for (int kc = 0; kc < 4; kc++)
                    mma_f16(d00, d01, d02, d03, a0[kc][0], a0[kc][1], a0[kc][2], a0[kc][3], b0[kc], b1[kc]);
                #pragma unroll
                for (int kc = 0; kc < 4; kc++)
                    mma_f16(d10, d11, d12, d13, a1[kc][0], a1[kc][1], a1[kc][2], a1[kc][3], b0[kc], b1[kc]);
                float2 r0v = *(const float2*)(XCF(0) + g * 68 + col0);
                float2 r1v = *(const float2*)(XCF(1) + g * 68 + col0);
                p7[0][jt * 2 + 0] = d00 + r0v.x; p7[0][jt * 2 + 1] = d01 + r0v.y;
                p7[1][jt * 2 + 0] = d10 + r1v.x; p7[1][jt * 2 + 1] = d11 + r1v.y;
            }
            #pragma unroll
            for (int e = 0; e < 2; e++) {
                float sg = (p7[e][0] + p7[e][1]) + (p7[e][2] + p7[e][3]);
                float qg = p7[e][0]*p7[e][0] + p7[e][1]*p7[e][1] + p7[e][2]*p7[e][2] + p7[e][3]*p7[e][3];
                sg += __shfl_xor_sync(0xffffffffu, sg, 1); sg += __shfl_xor_sync(0xffffffffu, sg, 2);
                qg += __shfl_xor_sync(0xffffffffu, qg, 1); qg += __shfl_xor_sync(0xffffffffu, qg, 2);
                if (tg == 0) {
                    float* ppe = PP(e);
                    ppe[g * 8 + warp]     = sg;
                    ppe[g * 8 + 4 + warp] = qg;
                }
            }
        }
        SUBBAR();

        // LN2 finish + scaled vector-atomic scatter (rows 0..7)
        #pragma unroll
        for (int e = 0; e < 2; e++) {
            bool ve = e ? v1 : v0;
            if (!ve) continue;
            int tgte = e ? t1i : t0i;
            float ice = e ? c1i : c0i;
            float* ppe = PP(e);
            float4 sx = *(const float4*)(ppe + g * 8);
            float4 sq = *(const float4*)(ppe + g * 8 + 4);
            float mu  = ((sx.x + sx.y) + (sx.z + sx.w)) * 0.015625f;
            float ex2 = ((sq.x + sq.y) + (sq.z + sq.w)) * 0.015625f;
            float rstd = rsqrtf(ex2 - mu * mu + 1e-5f);
            #pragma unroll
            for (int jt = 0; jt < 2; jt++) {
                int col0 = warp * 16 + jt * 8 + 2 * tg;
                float2 gg = *(const float2*)(s_b + 512 + col0);
                float2 be = *(const float2*)(s_b + 576 + col0);
                float o0 = ((p7[e][jt * 2 + 0] - mu) * rstd * gg.x + be.x) * ice;
                float o1 = ((p7[e][jt * 2 + 1] - mu) * rstd * gg.y + be.y) * ice;
                float* dst = hout + (size_t)tgte * 512 + g * 64 + col0;
                asm volatile("red.global.add.v2.f32 [%0], {%1,%2};"
                             :: "l"(dst), "f"(o0), "f"(o1) : "memory");
            }
        }
        // no trailing barrier: LN2 reads PP (next written at P4, 4 barriers away);
        // next P0 writes XSH/XCH/XCF rows 0..7, last read at P7 (behind barrier).
    }
}

__global__ void out_kernel(const float* __restrict__ ow, const float* __restrict__ ob,
                           float* __restrict__ out) {
    __shared__ float shs[8][64];
    int w = threadIdx.x >> 5, lane = threadIdx.x & 31;
    int n = blockIdx.x * 8 + w;
    if (n >= NN) return;
    const float* hr = g_hA + (size_t)n * 512;
    float lo = 0.f, hi = 0.f;
    #pragma unroll
    for (int c = 0; c < 8; c++) { lo += hr[c * 64 + lane]; hi += hr[c * 64 + 32 + lane]; }
    shs[w][lane] = lo; shs[w][lane + 32] = hi;
    __syncwarp();
    float z = -1e30f;
    if (lane < 16) {
        float acc = 8.f * ob[lane];
        const float* wr = ow + lane * 64;
        #pragma unroll
        for (int d = 0; d < 64; d++) acc = fmaf(shs[w][d], wr[d], acc);
        z = acc;
    }
    float m = z;
    #pragma unroll
    for (int off = 8; off; off >>= 1) m = fmaxf(m, __shfl_xor_sync(0xffffffffu, m, off, 16));
    float p = __expf(z - m);
    float s = p;
    #pragma unroll
    for (int off = 8; off; off >>= 1) s += __shfl_xor_sync(0xffffffffu, s, off, 16);
    if (lane < 16) out[n * 16 + lane] = p / s;
}

extern "C" void kernel_launch(void* const* d_in, const int* in_sizes, int n_in,
                              void* d_out, int out_size) {
    const float* x    = (const float*)d_in[0];
    const int*   ei   = (const int*)d_in[1];
    const float* numw = (const float*)d_in[2];
    const float* numb = (const float*)d_in[3];
    const float* bpw  = (const float*)d_in[4];
    const float* bpb  = (const float*)d_in[5];
    const float* ipw  = (const float*)d_in[6];
    const float* ipb  = (const float*)d_in[7];
    const float* opw  = (const float*)d_in[8];
    const float* opb  = (const float*)d_in[9];
    const float* g1   = (const float*)d_in[10];
    const float* b1   = (const float*)d_in[11];
    const float* g2   = (const float*)d_in[12];
    const float* b2   = (const float*)d_in[13];
    const float* w1   = (const float*)d_in[14];
    const float* fb1  = (const float*)d_in[15];
    const float* w2   = (const float*)d_in[16];
    const float* fb2  = (const float*)d_in[17];
    const float* ow   = (const float*)d_in[18];
    const float* ob   = (const float*)d_in[19];
    float* out = (float*)d_out;

    const int SMEM_BYTES = SMEM_WORDS * 4;
    cudaFuncSetAttribute(edge_kernel, cudaFuncAttributeMaxDynamicSharedMemorySize, SMEM_BYTES);

    int dev = 0, sms = 148;
    cudaGetDevice(&dev);
    cudaDeviceGetAttribute(&sms, cudaDevAttrMultiProcessorCount, dev);

    setup0_kernel<<<(NN * 128 + 255) / 256, 256>>>();
    detect_kernel<<<256, 256>>>(ei);
    embed_kernel<<<(NN * 512 + 255) / 256, 256>>>(x, numw, numb);
    count_kernel<<<(EE + 255) / 256, 256>>>(ei);
    fin_cnt_kernel<<<(NN + 255) / 256, 256>>>();

    edge_kernel<<<sms, 512, SMEM_BYTES>>>(ei, 0,
        bpw, bpb, ipw, ipb, opw, opb, g1, b1, g2, b2, w1, fb1, w2, fb2);

    zeroA_kernel<<<(NN * 128 + 255) / 256, 256>>>();
    edge_kernel<<<sms, 512, SMEM_BYTES>>>(ei, 1,
        bpw + 64 * 64, bpb + 64, ipw + 192 * 64, ipb + 192, opw + 64 * 64, opb + 64,
        g1 + 64, b1 + 64, g2 + 64, b2 + 64,
        w1 + 64 * 64, fb1 + 64, w2 + 64 * 64, fb2 + 64);

    out_kernel<<<(NN + 7) / 8, 256>>>(ow, ob, out);
}